// round 3
// baseline (speedup 1.0000x reference)
#include <cuda_runtime.h>
#include <math.h>

#define Bsz 32
#define Cch 128
#define Hh  64
#define Ww  64
#define OCn 128
#define En  8
#define Tn  256
#define HIDn 64
#define UPn 256
#define Rn  32
#define GHn 8

// ---- device scratch (no runtime allocation allowed) ----
__device__ float  g_mu[Bsz * Cch];
__device__ float  g_sd[Bsz * Cch];
__device__ float  g_rw[Bsz * En];
__device__ float4 g_weff4[(Bsz * OCn * Cch * 9) / 4];  // 18.9 MB mixed weights

// ============================================================
// Kernel 1: per-(b,c) mean / population-std over 64x64 spatial
// ============================================================
__global__ void stats_kernel(const float* __restrict__ x) {
    int bc = blockIdx.x;  // b*C + c
    const float4* p = (const float4*)(x + (size_t)bc * 4096);
    float s = 0.f, s2 = 0.f;
    for (int i = threadIdx.x; i < 1024; i += 256) {
        float4 v = p[i];
        s  += v.x + v.y + v.z + v.w;
        s2 += v.x * v.x + v.y * v.y + v.z * v.z + v.w * v.w;
    }
    __shared__ float sh[256], sh2[256];
    sh[threadIdx.x] = s; sh2[threadIdx.x] = s2;
    __syncthreads();
    for (int st = 128; st > 0; st >>= 1) {
        if (threadIdx.x < st) {
            sh[threadIdx.x]  += sh[threadIdx.x + st];
            sh2[threadIdx.x] += sh2[threadIdx.x + st];
        }
        __syncthreads();
    }
    if (threadIdx.x == 0) {
        float mu  = sh[0] * (1.f / 4096.f);
        float var = sh2[0] * (1.f / 4096.f) - mu * mu;
        g_mu[bc] = mu;
        g_sd[bc] = sqrtf(fmaxf(var, 0.f)) + 1e-6f;
    }
}

// ============================================================
// Kernel 2: router MLP chain + softmax -> g_rw[B][E]
// ============================================================
__global__ void router_kernel(
    const float* __restrict__ time_emb,
    const float* __restrict__ W_q,  const float* __restrict__ W_k,  const float* __restrict__ W_v,
    const float* __restrict__ W_g,  const float* __restrict__ b_g,
    const float* __restrict__ W_a1, const float* __restrict__ b_a1, const float* __restrict__ W_a2,
    const float* __restrict__ W_b1, const float* __restrict__ b_b1, const float* __restrict__ W_b2,
    const float* __restrict__ W_d,  const float* __restrict__ W_out)
{
    int b   = blockIdx.x;
    int tid = threadIdx.x;
    __shared__ float te[Tn], stats[2 * Cch], xh[HIDn], a1v[GHn], b1v[GHn],
                     tv[Rn], hv[UPn], xm[HIDn], lg[En];

    te[tid] = time_emb[b * Tn + tid];
    if (tid < Cch) {
        stats[tid]       = g_mu[b * Cch + tid];
        stats[Cch + tid] = g_sd[b * Cch + tid];
    }
    __syncthreads();

    if (tid < HIDn) {
        float q = 0.f, k = 0.f, v = 0.f;
        for (int j = 0; j < Tn; j++) q += W_q[tid * Tn + j] * te[j];
        for (int j = 0; j < 2 * Cch; j++) {
            float s = stats[j];
            k += W_k[tid * 2 * Cch + j] * s;
            v += W_v[tid * 2 * Cch + j] * s;
        }
        float g = q * k;
        xh[tid] = v / (1.f + expf(-g));
    }
    __syncthreads();

    if (tid < GHn) {
        float sa = b_a1[tid], sb = b_b1[tid];
        for (int i = 0; i < HIDn; i++) {
            sa += W_a1[tid * HIDn + i] * xh[i];
            sb += W_b1[tid * HIDn + i] * xh[i];
        }
        a1v[tid] = sa / (1.f + expf(-sa));
        b1v[tid] = sb / (1.f + expf(-sb));
    }
    __syncthreads();

    if (tid < Rn) {
        float acc = 0.f;
        for (int i = 0; i < HIDn; i++) {
            const float* wrow = W_a2 + (size_t)(i * Rn + tid) * GHn;
            float ai = 0.f;
            #pragma unroll
            for (int g = 0; g < GHn; g++) ai += wrow[g] * a1v[g];
            acc += xh[i] * ai;
        }
        tv[tid] = acc;
    }
    __syncthreads();

    {
        float gate = b_g[tid];
        for (int i = 0; i < HIDn; i++) gate += W_g[tid * HIDn + i] * xh[i];
        float dyn = 0.f;
        for (int r = 0; r < Rn; r++) {
            const float* wrow = W_b2 + (size_t)(r * UPn + tid) * GHn;
            float bm = 0.f;
            #pragma unroll
            for (int g = 0; g < GHn; g++) bm += wrow[g] * b1v[g];
            dyn += tv[r] * bm;
        }
        hv[tid] = (gate / (1.f + expf(-gate))) * dyn;
    }
    __syncthreads();

    if (tid < HIDn) {
        float m = xh[tid];
        for (int o = 0; o < UPn; o++) m += W_d[tid * UPn + o] * hv[o];
        xm[tid] = m;
    }
    __syncthreads();

    if (tid < En) {
        float l = 0.f;
        for (int i = 0; i < HIDn; i++) l += W_out[tid * HIDn + i] * xm[i];
        lg[tid] = l;
    }
    __syncthreads();

    if (tid == 0) {
        float mx = lg[0];
        for (int e = 1; e < En; e++) mx = fmaxf(mx, lg[e]);
        float ex[En]; float s = 0.f;
        for (int e = 0; e < En; e++) { ex[e] = expf(lg[e] - mx); s += ex[e]; }
        float inv = 1.f / s;
        for (int e = 0; e < En; e++) g_rw[b * En + e] = ex[e] * inv;
    }
}

// ============================================================
// Kernel 3: weff[b] = sum_e rw[b,e] * expert_w[e]  (float4)
// ============================================================
__global__ void mix_kernel(const float* __restrict__ expert_w) {
    int idx = blockIdx.x * 256 + threadIdx.x;
    const int per_b = (OCn * Cch * 9) / 4;
    int b  = idx / per_b;
    int r4 = idx - b * per_b;
    const float4* src = (const float4*)expert_w;
    float4 acc = make_float4(0.f, 0.f, 0.f, 0.f);
    #pragma unroll
    for (int e = 0; e < En; e++) {
        float w  = g_rw[b * En + e];
        float4 v = __ldg(&src[(size_t)e * per_b + r4]);
        acc.x += w * v.x; acc.y += w * v.y; acc.z += w * v.z; acc.w += w * v.w;
    }
    g_weff4[idx] = acc;
}

// ============================================================
// Kernel 4: per-batch 3x3 conv using packed FFMA2 (fma.rn.f32x2)
// CTA: (batch, 64 OCs, 8x32 spatial tile). 256 threads.
// Thread: 8 consecutive OCs (4 f32x2 pairs) x 8 rows.
// ============================================================
#define TH  8
#define TW  32
#define OCT 64
#define CC  8

__device__ __forceinline__ unsigned long long f32x2_dup(float v) {
    unsigned long long r;
    asm("mov.b64 %0, {%1, %1};" : "=l"(r) : "f"(v));
    return r;
}
__device__ __forceinline__ void ffma2(unsigned long long& acc,
                                      unsigned long long a,
                                      unsigned long long b) {
    asm("fma.rn.f32x2 %0, %1, %2, %0;" : "+l"(acc) : "l"(a), "l"(b));
}
__device__ __forceinline__ void f32x2_unpack(unsigned long long v, float& lo, float& hi) {
    asm("mov.b64 {%0, %1}, %2;" : "=f"(lo), "=f"(hi) : "l"(v));
}

__global__ void __launch_bounds__(256, 2) conv_kernel(const float* __restrict__ x,
                                                      float* __restrict__ out)
{
    __shared__ float sx[CC][TH + 2][TW + 4];  // [8][10][36]
    __shared__ float sw[CC][9][OCT + 2];      // [8][9][66] rows 8B-aligned (264B pitch)

    int b     = blockIdx.z;
    int oc0   = blockIdx.y * OCT;
    int tileY = (blockIdx.x >> 1) * TH;
    int tileX = (blockIdx.x & 1) * TW;
    int tid   = threadIdx.x;
    int ty    = tid >> 5;   // 0..7 : this thread owns ocs [oc0 + ty*8, +8)
    int tx    = tid & 31;   // 0..31: column within tile

    unsigned long long acc2[4][8];  // [oc-pair][pixel-row]
    #pragma unroll
    for (int jp = 0; jp < 4; jp++)
        #pragma unroll
        for (int p = 0; p < 8; p++) acc2[jp][p] = 0ull;

    const float* xb = x + (size_t)b * Cch * Hh * Ww;
    const float* wb = (const float*)g_weff4 +
                      (size_t)b * OCn * Cch * 9 + (size_t)oc0 * Cch * 9;

    for (int cb = 0; cb < Cch / CC; cb++) {
        // ---- load x tile (with halo, zero-padded)
        for (int i = tid; i < CC * 10 * 34; i += 256) {
            int cl  = i / 340;
            int rem = i - cl * 340;
            int r   = rem / 34;
            int cc  = rem - r * 34;
            int gy  = tileY + r - 1;
            int gx  = tileX + cc - 1;
            float v = 0.f;
            if ((unsigned)gy < 64u && (unsigned)gx < 64u)
                v = xb[((size_t)(cb * CC + cl) * 64 + gy) * 64 + gx];
            sx[cl][r][cc] = v;
        }
        // ---- load weight chunk : 64oc * 8c * 9
        for (int i = tid; i < OCT * CC * 9; i += 256) {
            int oc  = i / (CC * 9);
            int rem = i - oc * CC * 9;
            int cl  = rem / 9;
            int k   = rem - cl * 9;
            sw[cl][k][oc] = wb[(size_t)oc * Cch * 9 + (size_t)(cb * CC + cl) * 9 + k];
        }
        __syncthreads();

        #pragma unroll
        for (int cl = 0; cl < CC; cl++) {
            #pragma unroll
            for (int kw = 0; kw < 3; kw++) {
                // load 10-row x column once, duplicate into f32x2
                unsigned long long xd[10];
                #pragma unroll
                for (int r = 0; r < 10; r++)
                    xd[r] = f32x2_dup(sx[cl][r][tx + kw]);
                #pragma unroll
                for (int kh = 0; kh < 3; kh++) {
                    int k = kh * 3 + kw;
                    #pragma unroll
                    for (int jp = 0; jp < 4; jp++) {
                        // two consecutive oc weights in one 64-bit shared load
                        unsigned long long w2 =
                            *(const unsigned long long*)&sw[cl][k][ty * 8 + jp * 2];
                        #pragma unroll
                        for (int p = 0; p < 8; p++)
                            ffma2(acc2[jp][p], w2, xd[p + kh]);
                    }
                }
            }
        }
        __syncthreads();
    }

    // ---- store (coalesced: 32 consecutive cols per warp)
    #pragma unroll
    for (int jp = 0; jp < 4; jp++) {
        int ocA = oc0 + ty * 8 + jp * 2;
        #pragma unroll
        for (int p = 0; p < 8; p++) {
            float lo, hi;
            f32x2_unpack(acc2[jp][p], lo, hi);
            size_t base = (((size_t)b * OCn + ocA) * 64 + tileY + p) * 64 + tileX + tx;
            out[base]            = lo;
            out[base + 64 * 64]  = hi;
        }
    }
}

// ============================================================
extern "C" void kernel_launch(void* const* d_in, const int* in_sizes, int n_in,
                              void* d_out, int out_size)
{
    const float* x        = (const float*)d_in[0];
    const float* time_emb = (const float*)d_in[1];
    const float* expert_w = (const float*)d_in[2];
    const float* W_q      = (const float*)d_in[3];
    const float* W_k      = (const float*)d_in[4];
    const float* W_v      = (const float*)d_in[5];
    const float* W_g      = (const float*)d_in[6];
    const float* b_g      = (const float*)d_in[7];
    const float* W_a1     = (const float*)d_in[8];
    const float* b_a1     = (const float*)d_in[9];
    const float* W_a2     = (const float*)d_in[10];
    const float* W_b1     = (const float*)d_in[11];
    const float* b_b1     = (const float*)d_in[12];
    const float* W_b2     = (const float*)d_in[13];
    const float* W_d      = (const float*)d_in[14];
    const float* W_out    = (const float*)d_in[15];
    float* out = (float*)d_out;

    stats_kernel<<<Bsz * Cch, 256>>>(x);
    router_kernel<<<Bsz, 256>>>(time_emb, W_q, W_k, W_v, W_g, b_g,
                                W_a1, b_a1, W_a2, W_b1, b_b1, W_b2, W_d, W_out);
    mix_kernel<<<(Bsz * OCn * Cch * 9) / 4 / 256, 256>>>(expert_w);
    conv_kernel<<<dim3(16, 2, Bsz), 256>>>(x, out);
}

// round 4
// speedup vs baseline: 1.0011x; 1.0011x over previous
#include <cuda_runtime.h>
#include <math.h>

#define Bsz 32
#define Cch 128
#define Hh  64
#define Ww  64
#define OCn 128
#define En  8
#define Tn  256
#define HIDn 64
#define UPn 256
#define Rn  32
#define GHn 8

// ---- device scratch (no runtime allocation allowed) ----
__device__ float  g_mu[Bsz * Cch];
__device__ float  g_sd[Bsz * Cch];
__device__ float  g_rw[Bsz * En];
__device__ float4 g_weff4[(Bsz * OCn * Cch * 9) / 4];  // 18.9 MB mixed weights

// ============================================================
// Kernel 1: per-(b,c) mean / population-std over 64x64 spatial
// ============================================================
__global__ void stats_kernel(const float* __restrict__ x) {
    int bc = blockIdx.x;  // b*C + c
    const float4* p = (const float4*)(x + (size_t)bc * 4096);
    float s = 0.f, s2 = 0.f;
    for (int i = threadIdx.x; i < 1024; i += 256) {
        float4 v = p[i];
        s  += v.x + v.y + v.z + v.w;
        s2 += v.x * v.x + v.y * v.y + v.z * v.z + v.w * v.w;
    }
    __shared__ float sh[256], sh2[256];
    sh[threadIdx.x] = s; sh2[threadIdx.x] = s2;
    __syncthreads();
    for (int st = 128; st > 0; st >>= 1) {
        if (threadIdx.x < st) {
            sh[threadIdx.x]  += sh[threadIdx.x + st];
            sh2[threadIdx.x] += sh2[threadIdx.x + st];
        }
        __syncthreads();
    }
    if (threadIdx.x == 0) {
        float mu  = sh[0] * (1.f / 4096.f);
        float var = sh2[0] * (1.f / 4096.f) - mu * mu;
        g_mu[bc] = mu;
        g_sd[bc] = sqrtf(fmaxf(var, 0.f)) + 1e-6f;
    }
}

// ============================================================
// Kernel 2: router MLP chain + softmax -> g_rw[B][E]
// ============================================================
__global__ void router_kernel(
    const float* __restrict__ time_emb,
    const float* __restrict__ W_q,  const float* __restrict__ W_k,  const float* __restrict__ W_v,
    const float* __restrict__ W_g,  const float* __restrict__ b_g,
    const float* __restrict__ W_a1, const float* __restrict__ b_a1, const float* __restrict__ W_a2,
    const float* __restrict__ W_b1, const float* __restrict__ b_b1, const float* __restrict__ W_b2,
    const float* __restrict__ W_d,  const float* __restrict__ W_out)
{
    int b   = blockIdx.x;
    int tid = threadIdx.x;
    __shared__ float te[Tn], stats[2 * Cch], xh[HIDn], a1v[GHn], b1v[GHn],
                     tv[Rn], hv[UPn], xm[HIDn], lg[En];

    te[tid] = time_emb[b * Tn + tid];
    if (tid < Cch) {
        stats[tid]       = g_mu[b * Cch + tid];
        stats[Cch + tid] = g_sd[b * Cch + tid];
    }
    __syncthreads();

    if (tid < HIDn) {
        float q = 0.f, k = 0.f, v = 0.f;
        for (int j = 0; j < Tn; j++) q += W_q[tid * Tn + j] * te[j];
        for (int j = 0; j < 2 * Cch; j++) {
            float s = stats[j];
            k += W_k[tid * 2 * Cch + j] * s;
            v += W_v[tid * 2 * Cch + j] * s;
        }
        float g = q * k;
        xh[tid] = v / (1.f + expf(-g));
    }
    __syncthreads();

    if (tid < GHn) {
        float sa = b_a1[tid], sb = b_b1[tid];
        for (int i = 0; i < HIDn; i++) {
            sa += W_a1[tid * HIDn + i] * xh[i];
            sb += W_b1[tid * HIDn + i] * xh[i];
        }
        a1v[tid] = sa / (1.f + expf(-sa));
        b1v[tid] = sb / (1.f + expf(-sb));
    }
    __syncthreads();

    if (tid < Rn) {
        float acc = 0.f;
        for (int i = 0; i < HIDn; i++) {
            const float* wrow = W_a2 + (size_t)(i * Rn + tid) * GHn;
            float ai = 0.f;
            #pragma unroll
            for (int g = 0; g < GHn; g++) ai += wrow[g] * a1v[g];
            acc += xh[i] * ai;
        }
        tv[tid] = acc;
    }
    __syncthreads();

    {
        float gate = b_g[tid];
        for (int i = 0; i < HIDn; i++) gate += W_g[tid * HIDn + i] * xh[i];
        float dyn = 0.f;
        for (int r = 0; r < Rn; r++) {
            const float* wrow = W_b2 + (size_t)(r * UPn + tid) * GHn;
            float bm = 0.f;
            #pragma unroll
            for (int g = 0; g < GHn; g++) bm += wrow[g] * b1v[g];
            dyn += tv[r] * bm;
        }
        hv[tid] = (gate / (1.f + expf(-gate))) * dyn;
    }
    __syncthreads();

    if (tid < HIDn) {
        float m = xh[tid];
        for (int o = 0; o < UPn; o++) m += W_d[tid * UPn + o] * hv[o];
        xm[tid] = m;
    }
    __syncthreads();

    if (tid < En) {
        float l = 0.f;
        for (int i = 0; i < HIDn; i++) l += W_out[tid * HIDn + i] * xm[i];
        lg[tid] = l;
    }
    __syncthreads();

    if (tid == 0) {
        float mx = lg[0];
        for (int e = 1; e < En; e++) mx = fmaxf(mx, lg[e]);
        float ex[En]; float s = 0.f;
        for (int e = 0; e < En; e++) { ex[e] = expf(lg[e] - mx); s += ex[e]; }
        float inv = 1.f / s;
        for (int e = 0; e < En; e++) g_rw[b * En + e] = ex[e] * inv;
    }
}

// ============================================================
// Kernel 3: weff[b] = sum_e rw[b,e] * expert_w[e]  (float4)
// ============================================================
__global__ void mix_kernel(const float* __restrict__ expert_w) {
    int idx = blockIdx.x * 256 + threadIdx.x;
    const int per_b = (OCn * Cch * 9) / 4;
    int b  = idx / per_b;
    int r4 = idx - b * per_b;
    const float4* src = (const float4*)expert_w;
    float4 acc = make_float4(0.f, 0.f, 0.f, 0.f);
    #pragma unroll
    for (int e = 0; e < En; e++) {
        float w  = g_rw[b * En + e];
        float4 v = __ldg(&src[(size_t)e * per_b + r4]);
        acc.x += w * v.x; acc.y += w * v.y; acc.z += w * v.z; acc.w += w * v.w;
    }
    g_weff4[idx] = acc;
}

// ============================================================
// Kernel 4: per-batch 3x3 conv using packed FFMA2 (fma.rn.f32x2)
// CTA: (batch, 64 OCs, 8x32 spatial tile). 256 threads.
// Thread: 8 consecutive OCs (4 f32x2 pairs) x 8 rows.
// ============================================================
#define TH  8
#define TW  32
#define OCT 64
#define CC  8

__device__ __forceinline__ unsigned long long f32x2_dup(float v) {
    unsigned long long r;
    asm("mov.b64 %0, {%1, %1};" : "=l"(r) : "f"(v));
    return r;
}
__device__ __forceinline__ void ffma2(unsigned long long& acc,
                                      unsigned long long a,
                                      unsigned long long b) {
    asm("fma.rn.f32x2 %0, %1, %2, %0;" : "+l"(acc) : "l"(a), "l"(b));
}
__device__ __forceinline__ void f32x2_unpack(unsigned long long v, float& lo, float& hi) {
    asm("mov.b64 {%0, %1}, %2;" : "=f"(lo), "=f"(hi) : "l"(v));
}

__global__ void __launch_bounds__(256, 2) conv_kernel(const float* __restrict__ x,
                                                      float* __restrict__ out)
{
    __shared__ float sx[CC][TH + 2][TW + 4];  // [8][10][36]
    __shared__ float sw[CC][9][OCT + 2];      // [8][9][66] rows 8B-aligned (264B pitch)

    int b     = blockIdx.z;
    int oc0   = blockIdx.y * OCT;
    int tileY = (blockIdx.x >> 1) * TH;
    int tileX = (blockIdx.x & 1) * TW;
    int tid   = threadIdx.x;
    int ty    = tid >> 5;   // 0..7 : this thread owns ocs [oc0 + ty*8, +8)
    int tx    = tid & 31;   // 0..31: column within tile

    unsigned long long acc2[4][8];  // [oc-pair][pixel-row]
    #pragma unroll
    for (int jp = 0; jp < 4; jp++)
        #pragma unroll
        for (int p = 0; p < 8; p++) acc2[jp][p] = 0ull;

    const float* xb = x + (size_t)b * Cch * Hh * Ww;
    const float* wb = (const float*)g_weff4 +
                      (size_t)b * OCn * Cch * 9 + (size_t)oc0 * Cch * 9;

    for (int cb = 0; cb < Cch / CC; cb++) {
        // ---- load x tile (with halo, zero-padded)
        for (int i = tid; i < CC * 10 * 34; i += 256) {
            int cl  = i / 340;
            int rem = i - cl * 340;
            int r   = rem / 34;
            int cc  = rem - r * 34;
            int gy  = tileY + r - 1;
            int gx  = tileX + cc - 1;
            float v = 0.f;
            if ((unsigned)gy < 64u && (unsigned)gx < 64u)
                v = xb[((size_t)(cb * CC + cl) * 64 + gy) * 64 + gx];
            sx[cl][r][cc] = v;
        }
        // ---- load weight chunk : 64oc * 8c * 9
        for (int i = tid; i < OCT * CC * 9; i += 256) {
            int oc  = i / (CC * 9);
            int rem = i - oc * CC * 9;
            int cl  = rem / 9;
            int k   = rem - cl * 9;
            sw[cl][k][oc] = wb[(size_t)oc * Cch * 9 + (size_t)(cb * CC + cl) * 9 + k];
        }
        __syncthreads();

        #pragma unroll
        for (int cl = 0; cl < CC; cl++) {
            #pragma unroll
            for (int kw = 0; kw < 3; kw++) {
                // load 10-row x column once, duplicate into f32x2
                unsigned long long xd[10];
                #pragma unroll
                for (int r = 0; r < 10; r++)
                    xd[r] = f32x2_dup(sx[cl][r][tx + kw]);
                #pragma unroll
                for (int kh = 0; kh < 3; kh++) {
                    int k = kh * 3 + kw;
                    #pragma unroll
                    for (int jp = 0; jp < 4; jp++) {
                        // two consecutive oc weights in one 64-bit shared load
                        unsigned long long w2 =
                            *(const unsigned long long*)&sw[cl][k][ty * 8 + jp * 2];
                        #pragma unroll
                        for (int p = 0; p < 8; p++)
                            ffma2(acc2[jp][p], w2, xd[p + kh]);
                    }
                }
            }
        }
        __syncthreads();
    }

    // ---- store (coalesced: 32 consecutive cols per warp)
    #pragma unroll
    for (int jp = 0; jp < 4; jp++) {
        int ocA = oc0 + ty * 8 + jp * 2;
        #pragma unroll
        for (int p = 0; p < 8; p++) {
            float lo, hi;
            f32x2_unpack(acc2[jp][p], lo, hi);
            size_t base = (((size_t)b * OCn + ocA) * 64 + tileY + p) * 64 + tileX + tx;
            out[base]            = lo;
            out[base + 64 * 64]  = hi;
        }
    }
}

// ============================================================
extern "C" void kernel_launch(void* const* d_in, const int* in_sizes, int n_in,
                              void* d_out, int out_size)
{
    const float* x        = (const float*)d_in[0];
    const float* time_emb = (const float*)d_in[1];
    const float* expert_w = (const float*)d_in[2];
    const float* W_q      = (const float*)d_in[3];
    const float* W_k      = (const float*)d_in[4];
    const float* W_v      = (const float*)d_in[5];
    const float* W_g      = (const float*)d_in[6];
    const float* b_g      = (const float*)d_in[7];
    const float* W_a1     = (const float*)d_in[8];
    const float* b_a1     = (const float*)d_in[9];
    const float* W_a2     = (const float*)d_in[10];
    const float* W_b1     = (const float*)d_in[11];
    const float* b_b1     = (const float*)d_in[12];
    const float* W_b2     = (const float*)d_in[13];
    const float* W_d      = (const float*)d_in[14];
    const float* W_out    = (const float*)d_in[15];
    float* out = (float*)d_out;

    stats_kernel<<<Bsz * Cch, 256>>>(x);
    router_kernel<<<Bsz, 256>>>(time_emb, W_q, W_k, W_v, W_g, b_g,
                                W_a1, b_a1, W_a2, W_b1, b_b1, W_b2, W_d, W_out);
    mix_kernel<<<(Bsz * OCn * Cch * 9) / 4 / 256, 256>>>(expert_w);
    conv_kernel<<<dim3(16, 2, Bsz), 256>>>(x, out);
}

// round 8
// speedup vs baseline: 2.0036x; 2.0013x over previous
#include <cuda_runtime.h>
#include <cuda_bf16.h>
#include <cstdint>
#include <math.h>

#define Bsz 32
#define Cch 128
#define OCn 128
#define En  8
#define Tn  256
#define HIDn 64
#define UPn 256
#define Rn  32
#define GHn 8
#define PADW  66
#define PROWS (66*66)

// ---- device scratch ----
__device__ float g_mu[Bsz * Cch];
__device__ float g_sd[Bsz * Cch];
__device__ float g_rw[Bsz * En];
__device__ __align__(16) __nv_bfloat16 g_whi[Bsz * 9 * 2 * OCn * 64];
__device__ __align__(16) __nv_bfloat16 g_wlo[Bsz * 9 * 2 * OCn * 64];
__device__ __align__(16) __nv_bfloat16 g_xthi[(size_t)Bsz * PROWS * Cch];
__device__ __align__(16) __nv_bfloat16 g_xtlo[(size_t)Bsz * PROWS * Cch];

// ---- PTX helpers (baseline PTX only: cp.async / ldmatrix / mma.sync) ----
__device__ __forceinline__ uint32_t smem_u32(const void* p) {
    uint32_t a;
    asm("{ .reg .u64 t; cvta.to.shared.u64 t, %1; cvt.u32.u64 %0, t; }" : "=r"(a) : "l"(p));
    return a;
}
__device__ __forceinline__ void cp16(uint32_t dst, const void* src) {
    asm volatile("cp.async.cg.shared.global [%0], [%1], 16;" :: "r"(dst), "l"(src));
}
__device__ __forceinline__ void cp_commit() {
    asm volatile("cp.async.commit_group;" ::: "memory");
}
__device__ __forceinline__ void cp_wait1() {
    asm volatile("cp.async.wait_group 1;" ::: "memory");
}
__device__ __forceinline__ void cp_wait0() {
    asm volatile("cp.async.wait_group 0;" ::: "memory");
}
__device__ __forceinline__ void ldsm4(uint32_t* r, uint32_t addr) {
    asm volatile("ldmatrix.sync.aligned.m8n8.x4.shared.b16 {%0,%1,%2,%3}, [%4];"
                 : "=r"(r[0]), "=r"(r[1]), "=r"(r[2]), "=r"(r[3]) : "r"(addr));
}
__device__ __forceinline__ void mma_bf16(float* d, const uint32_t* a, const uint32_t* b) {
    asm volatile(
        "mma.sync.aligned.m16n8k16.row.col.f32.bf16.bf16.f32 "
        "{%0,%1,%2,%3}, {%4,%5,%6,%7}, {%8,%9}, {%0,%1,%2,%3};"
        : "+f"(d[0]), "+f"(d[1]), "+f"(d[2]), "+f"(d[3])
        : "r"(a[0]), "r"(a[1]), "r"(a[2]), "r"(a[3]), "r"(b[0]), "r"(b[1]));
}
__device__ __forceinline__ uint32_t swz(uint32_t off) { return off ^ ((off >> 3) & 0x70); }

// ============================================================
// stats
// ============================================================
__global__ void stats_kernel(const float* __restrict__ x) {
    int bc = blockIdx.x;
    const float4* p = (const float4*)(x + (size_t)bc * 4096);
    float s = 0.f, s2 = 0.f;
    for (int i = threadIdx.x; i < 1024; i += 256) {
        float4 v = p[i];
        s  += v.x + v.y + v.z + v.w;
        s2 += v.x * v.x + v.y * v.y + v.z * v.z + v.w * v.w;
    }
    __shared__ float sh[256], sh2[256];
    sh[threadIdx.x] = s; sh2[threadIdx.x] = s2;
    __syncthreads();
    for (int st = 128; st > 0; st >>= 1) {
        if (threadIdx.x < st) {
            sh[threadIdx.x]  += sh[threadIdx.x + st];
            sh2[threadIdx.x] += sh2[threadIdx.x + st];
        }
        __syncthreads();
    }
    if (threadIdx.x == 0) {
        float mu  = sh[0] * (1.f / 4096.f);
        float var = sh2[0] * (1.f / 4096.f) - mu * mu;
        g_mu[bc] = mu;
        g_sd[bc] = sqrtf(fmaxf(var, 0.f)) + 1e-6f;
    }
}

// ============================================================
// router
// ============================================================
__global__ void router_kernel(
    const float* __restrict__ time_emb,
    const float* __restrict__ W_q,  const float* __restrict__ W_k,  const float* __restrict__ W_v,
    const float* __restrict__ W_g,  const float* __restrict__ b_g,
    const float* __restrict__ W_a1, const float* __restrict__ b_a1, const float* __restrict__ W_a2,
    const float* __restrict__ W_b1, const float* __restrict__ b_b1, const float* __restrict__ W_b2,
    const float* __restrict__ W_d,  const float* __restrict__ W_out)
{
    int b = blockIdx.x, tid = threadIdx.x;
    __shared__ float te[Tn], sts[2*Cch], xh[HIDn], a1v[GHn], b1v[GHn],
                     tv[Rn], hv[UPn], xm[HIDn], lg[En];
    te[tid] = time_emb[b * Tn + tid];
    if (tid < Cch) { sts[tid] = g_mu[b*Cch+tid]; sts[Cch+tid] = g_sd[b*Cch+tid]; }
    __syncthreads();
    if (tid < HIDn) {
        float q = 0.f, k = 0.f, v = 0.f;
        for (int j = 0; j < Tn; j++) q += W_q[tid*Tn+j] * te[j];
        for (int j = 0; j < 2*Cch; j++) {
            float s = sts[j];
            k += W_k[tid*2*Cch+j] * s;
            v += W_v[tid*2*Cch+j] * s;
        }
        xh[tid] = v / (1.f + expf(-(q*k)));
    }
    __syncthreads();
    if (tid < GHn) {
        float sa = b_a1[tid], sb = b_b1[tid];
        for (int i = 0; i < HIDn; i++) { sa += W_a1[tid*HIDn+i]*xh[i]; sb += W_b1[tid*HIDn+i]*xh[i]; }
        a1v[tid] = sa / (1.f + expf(-sa));
        b1v[tid] = sb / (1.f + expf(-sb));
    }
    __syncthreads();
    if (tid < Rn) {
        float acc = 0.f;
        for (int i = 0; i < HIDn; i++) {
            const float* wr = W_a2 + (size_t)(i*Rn + tid)*GHn;
            float ai = 0.f;
            #pragma unroll
            for (int g = 0; g < GHn; g++) ai += wr[g]*a1v[g];
            acc += xh[i]*ai;
        }
        tv[tid] = acc;
    }
    __syncthreads();
    {
        float gate = b_g[tid];
        for (int i = 0; i < HIDn; i++) gate += W_g[tid*HIDn+i]*xh[i];
        float dyn = 0.f;
        for (int r = 0; r < Rn; r++) {
            const float* wr = W_b2 + (size_t)(r*UPn + tid)*GHn;
            float bm = 0.f;
            #pragma unroll
            for (int g = 0; g < GHn; g++) bm += wr[g]*b1v[g];
            dyn += tv[r]*bm;
        }
        hv[tid] = (gate / (1.f + expf(-gate))) * dyn;
    }
    __syncthreads();
    if (tid < HIDn) {
        float m = xh[tid];
        for (int o = 0; o < UPn; o++) m += W_d[tid*UPn+o]*hv[o];
        xm[tid] = m;
    }
    __syncthreads();
    if (tid < En) {
        float l = 0.f;
        for (int i = 0; i < HIDn; i++) l += W_out[tid*HIDn+i]*xm[i];
        lg[tid] = l;
    }
    __syncthreads();
    if (tid == 0) {
        float mx = lg[0];
        for (int e = 1; e < En; e++) mx = fmaxf(mx, lg[e]);
        float ex[En]; float s = 0.f;
        for (int e = 0; e < En; e++) { ex[e] = expf(lg[e]-mx); s += ex[e]; }
        float inv = 1.f / s;
        for (int e = 0; e < En; e++) g_rw[b*En+e] = ex[e]*inv;
    }
}

// ============================================================
// mix: weff -> bf16 hi/lo tiles  [b][tap][chunk][oc][64c]
// ============================================================
__global__ void mix_kernel(const float* __restrict__ expert_w) {
    int idx = blockIdx.x * 256 + threadIdx.x;
    int b  = idx >> 14;
    int oc = (idx >> 7) & 127;
    int c  = idx & 127;
    float acc[9];
    #pragma unroll
    for (int k = 0; k < 9; k++) acc[k] = 0.f;
    #pragma unroll
    for (int e = 0; e < En; e++) {
        float w = g_rw[b*En + e];
        const float* src = expert_w + (size_t)((e*128 + oc)*128 + c) * 9;
        #pragma unroll
        for (int k = 0; k < 9; k++) acc[k] += w * src[k];
    }
    int cx = c >> 6, cl = c & 63;
    #pragma unroll
    for (int k = 0; k < 9; k++) {
        int d = ((b*9 + k)*2 + cx)*8192 + oc*64 + cl;
        __nv_bfloat16 hi = __float2bfloat16(acc[k]);
        __nv_bfloat16 lo = __float2bfloat16(acc[k] - __bfloat162float(hi));
        g_whi[d] = hi; g_wlo[d] = lo;
    }
}

// ============================================================
// transpose x -> padded NHWC bf16 hi/lo.  CTA = (y, b)
// ============================================================
__global__ void transpose_kernel(const float* __restrict__ x) {
    __shared__ float s[128][65];
    int y = blockIdx.x, b = blockIdx.y, tid = threadIdx.x;
    const float* xb = x + (size_t)b * Cch * 4096;
    for (int i = tid; i < 8192; i += 256) {
        int c = i >> 6, xx = i & 63;
        s[c][xx] = xb[(size_t)c * 4096 + y * 64 + xx];
    }
    __syncthreads();
    size_t base = ((size_t)b * PROWS + (size_t)(y + 1) * PADW + 1) * 128;
    for (int i = tid; i < 8192; i += 256) {
        int px = i >> 7, c = i & 127;
        float v = s[c][px];
        __nv_bfloat16 hi = __float2bfloat16(v);
        __nv_bfloat16 lo = __float2bfloat16(v - __bfloat162float(hi));
        size_t d = base + (size_t)px * 128 + c;
        g_xthi[d] = hi; g_xtlo[d] = lo;
    }
}

// border zero-fill
__global__ void border_kernel() {
    int idx = blockIdx.x * 256 + threadIdx.x;
    int b = idx / (260 * 128);
    int rem = idx - b * 260 * 128;
    int p = rem >> 7, c = rem & 127;
    int pr, pc;
    if (p < 132) { pr = (p < 66) ? 0 : 65; pc = p % 66; }
    else { int q = p - 132; pc = (q < 64) ? 0 : 65; pr = 1 + (q & 63); }
    size_t d = ((size_t)b * PROWS + pr * PADW + pc) * 128 + c;
    g_xthi[d] = __float2bfloat16(0.f);
    g_xtlo[d] = __float2bfloat16(0.f);
}

// ============================================================
// conv via mma.sync bf16 (HMMA).  CTA = (2 image rows, b).
// M=128 oc x N=128 px, K = 18 chunks of 64c (9 taps x 2).
// 8 warps: warp tile 64oc x 32px.  3-product hi/lo split.
// Smem stage = Ah|Al|Bh|Bl 16KB each; 2 stages (128KB).
// ============================================================
#define STG 65536
#define SA_H 0
#define SA_L 16384
#define SB_H 32768
#define SB_L 49152
#define CONV_SMEM (2*STG)

__global__ void __launch_bounds__(256)
conv_mma_kernel(float* __restrict__ out)
{
    extern __shared__ char dsm[];
    const uint32_t sb = smem_u32(dsm);
    const int tid  = threadIdx.x;
    const int lane = tid & 31;
    const int wid  = tid >> 5;
    const int wm   = wid & 1;          // 0..1 : 64-oc block
    const int wn   = wid >> 1;         // 0..3 : 32-px block
    const int b    = blockIdx.y;
    const int y0   = blockIdx.x * 2;   // two image rows per CTA

    const char* xh_base = (const char*)g_xthi + (size_t)b * PROWS * 256;
    const char* xl_base = (const char*)g_xtlo + (size_t)b * PROWS * 256;

    float acc[4][4][4];
    #pragma unroll
    for (int mi = 0; mi < 4; mi++)
        #pragma unroll
        for (int ni = 0; ni < 4; ni++)
            #pragma unroll
            for (int k = 0; k < 4; k++) acc[mi][ni][k] = 0.f;

    // ---- loader: one chunk (tap, cx) into stage s
    auto load_chunk = [&](int ch, int s) {
        int tap = ch >> 1, cx = ch & 1;
        int dy = tap / 3, dx = tap % 3;
        uint32_t so = sb + s * STG;
        const char* ah = (const char*)g_whi + (size_t)((b*9 + tap)*2 + cx) * 16384;
        const char* al = (const char*)g_wlo + (size_t)((b*9 + tap)*2 + cx) * 16384;
        // A: 1024 16B units each
        for (int i = tid; i < 1024; i += 256) {
            uint32_t d = swz((uint32_t)i * 16);
            cp16(so + SA_H + d, ah + i * 16);
            cp16(so + SA_L + d, al + i * 16);
        }
        // B: 128 px rows x 128B (chunk half of 256B pixel row)
        for (int i = tid; i < 1024; i += 256) {
            int lr = i >> 3, u = i & 7;
            int p = (y0 + (lr >> 6) + dy) * PADW + dx + (lr & 63);
            size_t g = (size_t)p * 256 + cx * 128 + u * 16;
            uint32_t d = swz((uint32_t)i * 16);
            cp16(so + SB_H + d, xh_base + g);
            cp16(so + SB_L + d, xl_base + g);
        }
        cp_commit();
    };

    load_chunk(0, 0);

    for (int ch = 0; ch < 18; ch++) {
        if (ch < 17) load_chunk(ch + 1, (ch + 1) & 1);
        if (ch < 17) cp_wait1(); else cp_wait0();
        __syncthreads();

        uint32_t so = sb + (ch & 1) * STG;
        // per-lane ldmatrix address pieces
        int arow = wm * 64 + (lane & 15);           // + mi*16
        int acol16 = (lane >> 4) * 16;              // 0 or 16 bytes
        int brow = wn * 32 + ((lane >> 4) << 3) + (lane & 7);  // + np*16
        int bcol16 = ((lane >> 3) & 1) * 16;

        #pragma unroll
        for (int ks = 0; ks < 4; ks++) {
            uint32_t ah[4][4], al[4][4], bh[4][2], bl[4][2];
            #pragma unroll
            for (int mi = 0; mi < 4; mi++) {
                uint32_t off = swz((uint32_t)(arow + mi * 16) * 128 + ks * 32 + acol16);
                ldsm4(ah[mi], so + SA_H + off);
                ldsm4(al[mi], so + SA_L + off);
            }
            #pragma unroll
            for (int np = 0; np < 2; np++) {
                uint32_t off = swz((uint32_t)(brow + np * 16) * 128 + ks * 32 + bcol16);
                uint32_t t[4];
                ldsm4(t, so + SB_H + off);
                bh[2*np][0] = t[0]; bh[2*np][1] = t[1];
                bh[2*np+1][0] = t[2]; bh[2*np+1][1] = t[3];
                ldsm4(t, so + SB_L + off);
                bl[2*np][0] = t[0]; bl[2*np][1] = t[1];
                bl[2*np+1][0] = t[2]; bl[2*np+1][1] = t[3];
            }
            #pragma unroll
            for (int mi = 0; mi < 4; mi++)
                #pragma unroll
                for (int ni = 0; ni < 4; ni++) {
                    mma_bf16(acc[mi][ni], ah[mi], bh[ni]);
                    mma_bf16(acc[mi][ni], ah[mi], bl[ni]);
                    mma_bf16(acc[mi][ni], al[mi], bh[ni]);
                }
        }
        __syncthreads();
    }

    // ---- epilogue: direct stores
    int gid = lane >> 2, q = lane & 3;
    int pxbase = blockIdx.x * 128 + wn * 32;
    #pragma unroll
    for (int mi = 0; mi < 4; mi++) {
        int oc = wm * 64 + mi * 16 + gid;
        #pragma unroll
        for (int ni = 0; ni < 4; ni++) {
            int px = pxbase + ni * 8 + 2 * q;
            size_t base0 = ((size_t)(b * 128 + oc)) * 4096 + px;
            float2 v0 = make_float2(acc[mi][ni][0], acc[mi][ni][1]);
            float2 v1 = make_float2(acc[mi][ni][2], acc[mi][ni][3]);
            *(float2*)(out + base0)          = v0;
            *(float2*)(out + base0 + 8*4096) = v1;   // row gid+8
        }
    }
}

// ============================================================
extern "C" void kernel_launch(void* const* d_in, const int* in_sizes, int n_in,
                              void* d_out, int out_size)
{
    const float* x        = (const float*)d_in[0];
    const float* time_emb = (const float*)d_in[1];
    const float* expert_w = (const float*)d_in[2];
    const float* W_q  = (const float*)d_in[3];
    const float* W_k  = (const float*)d_in[4];
    const float* W_v  = (const float*)d_in[5];
    const float* W_g  = (const float*)d_in[6];
    const float* b_g  = (const float*)d_in[7];
    const float* W_a1 = (const float*)d_in[8];
    const float* b_a1 = (const float*)d_in[9];
    const float* W_a2 = (const float*)d_in[10];
    const float* W_b1 = (const float*)d_in[11];
    const float* b_b1 = (const float*)d_in[12];
    const float* W_b2 = (const float*)d_in[13];
    const float* W_d  = (const float*)d_in[14];
    const float* W_out= (const float*)d_in[15];
    float* out = (float*)d_out;

    cudaFuncSetAttribute(conv_mma_kernel,
                         cudaFuncAttributeMaxDynamicSharedMemorySize, CONV_SMEM);

    stats_kernel<<<Bsz * Cch, 256>>>(x);
    router_kernel<<<Bsz, 256>>>(time_emb, W_q, W_k, W_v, W_g, b_g,
                                W_a1, b_a1, W_a2, W_b1, b_b1, W_b2, W_d, W_out);
    mix_kernel<<<(Bsz * 128 * 128) / 256, 256>>>(expert_w);
    transpose_kernel<<<dim3(64, Bsz), 256>>>(x);
    border_kernel<<<(Bsz * 260 * 128) / 256, 256>>>();
    conv_mma_kernel<<<dim3(32, Bsz), 256, CONV_SMEM>>>(out);
}

// round 9
// speedup vs baseline: 2.0787x; 1.0375x over previous
#include <cuda_runtime.h>
#include <cuda_bf16.h>
#include <cstdint>
#include <math.h>

#define Bsz 32
#define Cch 128
#define OCn 128
#define En  8
#define Tn  256
#define HIDn 64
#define UPn 256
#define Rn  32
#define GHn 8
#define PADW  66
#define PROWS (66*66)

// ---- device scratch ----
__device__ float g_ps [Bsz * 64 * Cch];   // partial sums  [b][y][c]
__device__ float g_ps2[Bsz * 64 * Cch];   // partial sumsq [b][y][c]
__device__ float g_rw[Bsz * En];
__device__ __align__(16) __nv_bfloat16 g_whi[Bsz * 9 * 2 * OCn * 64];
__device__ __align__(16) __nv_bfloat16 g_wlo[Bsz * 9 * 2 * OCn * 64];
__device__ __align__(16) __nv_bfloat16 g_xthi[(size_t)Bsz * PROWS * Cch];
__device__ __align__(16) __nv_bfloat16 g_xtlo[(size_t)Bsz * PROWS * Cch];

// ---- PTX helpers (baseline PTX only) ----
__device__ __forceinline__ uint32_t smem_u32(const void* p) {
    uint32_t a;
    asm("{ .reg .u64 t; cvta.to.shared.u64 t, %1; cvt.u32.u64 %0, t; }" : "=r"(a) : "l"(p));
    return a;
}
__device__ __forceinline__ void cp16(uint32_t dst, const void* src) {
    asm volatile("cp.async.cg.shared.global [%0], [%1], 16;" :: "r"(dst), "l"(src));
}
__device__ __forceinline__ void cp_commit() {
    asm volatile("cp.async.commit_group;" ::: "memory");
}
__device__ __forceinline__ void cp_wait1() {
    asm volatile("cp.async.wait_group 1;" ::: "memory");
}
__device__ __forceinline__ void cp_wait0() {
    asm volatile("cp.async.wait_group 0;" ::: "memory");
}
__device__ __forceinline__ void ldsm4(uint32_t* r, uint32_t addr) {
    asm volatile("ldmatrix.sync.aligned.m8n8.x4.shared.b16 {%0,%1,%2,%3}, [%4];"
                 : "=r"(r[0]), "=r"(r[1]), "=r"(r[2]), "=r"(r[3]) : "r"(addr));
}
__device__ __forceinline__ void mma_bf16(float* d, const uint32_t* a, const uint32_t* b) {
    asm volatile(
        "mma.sync.aligned.m16n8k16.row.col.f32.bf16.bf16.f32 "
        "{%0,%1,%2,%3}, {%4,%5,%6,%7}, {%8,%9}, {%0,%1,%2,%3};"
        : "+f"(d[0]), "+f"(d[1]), "+f"(d[2]), "+f"(d[3])
        : "r"(a[0]), "r"(a[1]), "r"(a[2]), "r"(a[3]), "r"(b[0]), "r"(b[1]));
}
__device__ __forceinline__ uint32_t swz(uint32_t off) { return off ^ ((off >> 3) & 0x70); }

// ============================================================
// Launch 1: prep = transpose + partial stats + border zeroing
// CTA = (y, b), 256 threads
// ============================================================
__global__ void prep_kernel(const float* __restrict__ x) {
    __shared__ float s[128][65];
    int y = blockIdx.x, b = blockIdx.y, tid = threadIdx.x;
    const float* xb = x + (size_t)b * Cch * 4096;
    for (int i = tid; i < 8192; i += 256) {
        int c = i >> 6, xx = i & 63;
        s[c][xx] = xb[(size_t)c * 4096 + y * 64 + xx];
    }
    __syncthreads();

    // partial stats for this (b, y): sums over 64 x-positions per channel
    if (tid < 128) {
        float s1 = 0.f, s2 = 0.f;
        #pragma unroll 8
        for (int xx = 0; xx < 64; xx++) {
            float v = s[tid][xx];
            s1 += v; s2 += v * v;
        }
        int d = (b * 64 + y) * 128 + tid;
        g_ps[d] = s1; g_ps2[d] = s2;
    }

    // transposed padded NHWC bf16 hi/lo
    size_t base = ((size_t)b * PROWS + (size_t)(y + 1) * PADW + 1) * 128;
    for (int i = tid; i < 8192; i += 256) {
        int px = i >> 7, c = i & 127;
        float v = s[c][px];
        __nv_bfloat16 hi = __float2bfloat16(v);
        __nv_bfloat16 lo = __float2bfloat16(v - __bfloat162float(hi));
        size_t d = base + (size_t)px * 128 + c;
        g_xthi[d] = hi; g_xtlo[d] = lo;
    }

    // border: this padded row's col 0 and col 65
    __nv_bfloat16 z = __float2bfloat16(0.f);
    if (tid < 128) {
        size_t r = ((size_t)b * PROWS + (size_t)(y + 1) * PADW) * 128;
        g_xthi[r + tid] = z;             g_xtlo[r + tid] = z;
        g_xthi[r + 65 * 128 + tid] = z;  g_xtlo[r + 65 * 128 + tid] = z;
    }
    // padded rows 0 and 65 (full 66 px) handled by y==0 / y==63
    if (y == 0) {
        size_t r = (size_t)b * PROWS * 128;
        for (int i = tid; i < 66 * 128; i += 256) { g_xthi[r + i] = z; g_xtlo[r + i] = z; }
    }
    if (y == 63) {
        size_t r = ((size_t)b * PROWS + 65 * PADW) * 128;
        for (int i = tid; i < 66 * 128; i += 256) { g_xthi[r + i] = z; g_xtlo[r + i] = z; }
    }
}

// ============================================================
// Launch 2: router (finalizes stats from partials)
// ============================================================
__global__ void router_kernel(
    const float* __restrict__ time_emb,
    const float* __restrict__ W_q,  const float* __restrict__ W_k,  const float* __restrict__ W_v,
    const float* __restrict__ W_g,  const float* __restrict__ b_g,
    const float* __restrict__ W_a1, const float* __restrict__ b_a1, const float* __restrict__ W_a2,
    const float* __restrict__ W_b1, const float* __restrict__ b_b1, const float* __restrict__ W_b2,
    const float* __restrict__ W_d,  const float* __restrict__ W_out)
{
    int b = blockIdx.x, tid = threadIdx.x;
    __shared__ float te[Tn], sts[2*Cch], xh[HIDn], a1v[GHn], b1v[GHn],
                     tv[Rn], hv[UPn], xm[HIDn], lg[En];
    te[tid] = time_emb[b * Tn + tid];
    if (tid < Cch) {
        float s1 = 0.f, s2 = 0.f;
        for (int y = 0; y < 64; y++) {
            int d = (b * 64 + y) * 128 + tid;
            s1 += g_ps[d]; s2 += g_ps2[d];
        }
        float mu  = s1 * (1.f / 4096.f);
        float var = s2 * (1.f / 4096.f) - mu * mu;
        sts[tid]       = mu;
        sts[Cch + tid] = sqrtf(fmaxf(var, 0.f)) + 1e-6f;
    }
    __syncthreads();
    if (tid < HIDn) {
        float q = 0.f, k = 0.f, v = 0.f;
        for (int j = 0; j < Tn; j++) q += W_q[tid*Tn+j] * te[j];
        for (int j = 0; j < 2*Cch; j++) {
            float s = sts[j];
            k += W_k[tid*2*Cch+j] * s;
            v += W_v[tid*2*Cch+j] * s;
        }
        xh[tid] = v / (1.f + expf(-(q*k)));
    }
    __syncthreads();
    if (tid < GHn) {
        float sa = b_a1[tid], sb = b_b1[tid];
        for (int i = 0; i < HIDn; i++) { sa += W_a1[tid*HIDn+i]*xh[i]; sb += W_b1[tid*HIDn+i]*xh[i]; }
        a1v[tid] = sa / (1.f + expf(-sa));
        b1v[tid] = sb / (1.f + expf(-sb));
    }
    __syncthreads();
    if (tid < Rn) {
        float acc = 0.f;
        for (int i = 0; i < HIDn; i++) {
            const float* wr = W_a2 + (size_t)(i*Rn + tid)*GHn;
            float ai = 0.f;
            #pragma unroll
            for (int g = 0; g < GHn; g++) ai += wr[g]*a1v[g];
            acc += xh[i]*ai;
        }
        tv[tid] = acc;
    }
    __syncthreads();
    {
        float gate = b_g[tid];
        for (int i = 0; i < HIDn; i++) gate += W_g[tid*HIDn+i]*xh[i];
        float dyn = 0.f;
        for (int r = 0; r < Rn; r++) {
            const float* wr = W_b2 + (size_t)(r*UPn + tid)*GHn;
            float bm = 0.f;
            #pragma unroll
            for (int g = 0; g < GHn; g++) bm += wr[g]*b1v[g];
            dyn += tv[r]*bm;
        }
        hv[tid] = (gate / (1.f + expf(-gate))) * dyn;
    }
    __syncthreads();
    if (tid < HIDn) {
        float m = xh[tid];
        for (int o = 0; o < UPn; o++) m += W_d[tid*UPn+o]*hv[o];
        xm[tid] = m;
    }
    __syncthreads();
    if (tid < En) {
        float l = 0.f;
        for (int i = 0; i < HIDn; i++) l += W_out[tid*HIDn+i]*xm[i];
        lg[tid] = l;
    }
    __syncthreads();
    if (tid == 0) {
        float mx = lg[0];
        for (int e = 1; e < En; e++) mx = fmaxf(mx, lg[e]);
        float ex[En]; float s = 0.f;
        for (int e = 0; e < En; e++) { ex[e] = expf(lg[e]-mx); s += ex[e]; }
        float inv = 1.f / s;
        for (int e = 0; e < En; e++) g_rw[b*En+e] = ex[e]*inv;
    }
}

// ============================================================
// Launch 3: mix -> bf16 hi/lo tiles  [b][tap][chunk][oc][64c]
// ============================================================
__global__ void mix_kernel(const float* __restrict__ expert_w) {
    int idx = blockIdx.x * 256 + threadIdx.x;
    int b  = idx >> 14;
    int oc = (idx >> 7) & 127;
    int c  = idx & 127;
    float acc[9];
    #pragma unroll
    for (int k = 0; k < 9; k++) acc[k] = 0.f;
    #pragma unroll
    for (int e = 0; e < En; e++) {
        float w = g_rw[b*En + e];
        const float* src = expert_w + (size_t)((e*128 + oc)*128 + c) * 9;
        #pragma unroll
        for (int k = 0; k < 9; k++) acc[k] += w * src[k];
    }
    int cx = c >> 6, cl = c & 63;
    #pragma unroll
    for (int k = 0; k < 9; k++) {
        int d = ((b*9 + k)*2 + cx)*8192 + oc*64 + cl;
        __nv_bfloat16 hi = __float2bfloat16(acc[k]);
        __nv_bfloat16 lo = __float2bfloat16(acc[k] - __bfloat162float(hi));
        g_whi[d] = hi; g_wlo[d] = lo;
    }
}

// ============================================================
// Launch 4 (profiled slot): conv via mma.sync bf16 (HMMA)
// CTA = (2 image rows, b). M=128 oc x N=128 px, 18 K-chunks of 64c.
// ============================================================
#define STG 65536
#define SA_H 0
#define SA_L 16384
#define SB_H 32768
#define SB_L 49152
#define CONV_SMEM (2*STG)

__global__ void __launch_bounds__(256)
conv_mma_kernel(float* __restrict__ out)
{
    extern __shared__ char dsm[];
    const uint32_t sb = smem_u32(dsm);
    const int tid  = threadIdx.x;
    const int lane = tid & 31;
    const int wid  = tid >> 5;
    const int wm   = wid & 1;
    const int wn   = wid >> 1;
    const int b    = blockIdx.y;
    const int y0   = blockIdx.x * 2;

    const char* xh_base = (const char*)g_xthi + (size_t)b * PROWS * 256;
    const char* xl_base = (const char*)g_xtlo + (size_t)b * PROWS * 256;

    float acc[4][4][4];
    #pragma unroll
    for (int mi = 0; mi < 4; mi++)
        #pragma unroll
        for (int ni = 0; ni < 4; ni++)
            #pragma unroll
            for (int k = 0; k < 4; k++) acc[mi][ni][k] = 0.f;

    auto load_chunk = [&](int ch, int s) {
        int tap = ch >> 1, cx = ch & 1;
        int dy = tap / 3, dx = tap % 3;
        uint32_t so = sb + s * STG;
        const char* ah = (const char*)g_whi + (size_t)((b*9 + tap)*2 + cx) * 16384;
        const char* al = (const char*)g_wlo + (size_t)((b*9 + tap)*2 + cx) * 16384;
        for (int i = tid; i < 1024; i += 256) {
            uint32_t d = swz((uint32_t)i * 16);
            cp16(so + SA_H + d, ah + i * 16);
            cp16(so + SA_L + d, al + i * 16);
        }
        for (int i = tid; i < 1024; i += 256) {
            int lr = i >> 3, u = i & 7;
            int p = (y0 + (lr >> 6) + dy) * PADW + dx + (lr & 63);
            size_t g = (size_t)p * 256 + cx * 128 + u * 16;
            uint32_t d = swz((uint32_t)i * 16);
            cp16(so + SB_H + d, xh_base + g);
            cp16(so + SB_L + d, xl_base + g);
        }
        cp_commit();
    };

    load_chunk(0, 0);

    for (int ch = 0; ch < 18; ch++) {
        if (ch < 17) load_chunk(ch + 1, (ch + 1) & 1);
        if (ch < 17) cp_wait1(); else cp_wait0();
        __syncthreads();

        uint32_t so = sb + (ch & 1) * STG;
        int arow = wm * 64 + (lane & 15);
        int acol16 = (lane >> 4) * 16;
        int brow = wn * 32 + ((lane >> 4) << 3) + (lane & 7);
        int bcol16 = ((lane >> 3) & 1) * 16;

        #pragma unroll
        for (int ks = 0; ks < 4; ks++) {
            uint32_t ah[4][4], al[4][4], bh[4][2], bl[4][2];
            #pragma unroll
            for (int mi = 0; mi < 4; mi++) {
                uint32_t off = swz((uint32_t)(arow + mi * 16) * 128 + ks * 32 + acol16);
                ldsm4(ah[mi], so + SA_H + off);
                ldsm4(al[mi], so + SA_L + off);
            }
            #pragma unroll
            for (int np = 0; np < 2; np++) {
                uint32_t off = swz((uint32_t)(brow + np * 16) * 128 + ks * 32 + bcol16);
                uint32_t t[4];
                ldsm4(t, so + SB_H + off);
                bh[2*np][0] = t[0]; bh[2*np][1] = t[1];
                bh[2*np+1][0] = t[2]; bh[2*np+1][1] = t[3];
                ldsm4(t, so + SB_L + off);
                bl[2*np][0] = t[0]; bl[2*np][1] = t[1];
                bl[2*np+1][0] = t[2]; bl[2*np+1][1] = t[3];
            }
            #pragma unroll
            for (int mi = 0; mi < 4; mi++)
                #pragma unroll
                for (int ni = 0; ni < 4; ni++) {
                    mma_bf16(acc[mi][ni], ah[mi], bh[ni]);
                    mma_bf16(acc[mi][ni], ah[mi], bl[ni]);
                    mma_bf16(acc[mi][ni], al[mi], bh[ni]);
                }
        }
        __syncthreads();
    }

    int gid = lane >> 2, q = lane & 3;
    int pxbase = blockIdx.x * 128 + wn * 32;
    #pragma unroll
    for (int mi = 0; mi < 4; mi++) {
        int oc = wm * 64 + mi * 16 + gid;
        #pragma unroll
        for (int ni = 0; ni < 4; ni++) {
            int px = pxbase + ni * 8 + 2 * q;
            size_t base0 = ((size_t)(b * 128 + oc)) * 4096 + px;
            float2 v0 = make_float2(acc[mi][ni][0], acc[mi][ni][1]);
            float2 v1 = make_float2(acc[mi][ni][2], acc[mi][ni][3]);
            *(float2*)(out + base0)          = v0;
            *(float2*)(out + base0 + 8*4096) = v1;
        }
    }
}

// ============================================================
extern "C" void kernel_launch(void* const* d_in, const int* in_sizes, int n_in,
                              void* d_out, int out_size)
{
    const float* x        = (const float*)d_in[0];
    const float* time_emb = (const float*)d_in[1];
    const float* expert_w = (const float*)d_in[2];
    const float* W_q  = (const float*)d_in[3];
    const float* W_k  = (const float*)d_in[4];
    const float* W_v  = (const float*)d_in[5];
    const float* W_g  = (const float*)d_in[6];
    const float* b_g  = (const float*)d_in[7];
    const float* W_a1 = (const float*)d_in[8];
    const float* b_a1 = (const float*)d_in[9];
    const float* W_a2 = (const float*)d_in[10];
    const float* W_b1 = (const float*)d_in[11];
    const float* b_b1 = (const float*)d_in[12];
    const float* W_b2 = (const float*)d_in[13];
    const float* W_d  = (const float*)d_in[14];
    const float* W_out= (const float*)d_in[15];
    float* out = (float*)d_out;

    cudaFuncSetAttribute(conv_mma_kernel,
                         cudaFuncAttributeMaxDynamicSharedMemorySize, CONV_SMEM);

    prep_kernel<<<dim3(64, Bsz), 256>>>(x);
    router_kernel<<<Bsz, 256>>>(time_emb, W_q, W_k, W_v, W_g, b_g,
                                W_a1, b_a1, W_a2, W_b1, b_b1, W_b2, W_d, W_out);
    mix_kernel<<<(Bsz * 128 * 128) / 256, 256>>>(expert_w);
    conv_mma_kernel<<<dim3(32, Bsz), 256, CONV_SMEM>>>(out);
}

// round 10
// speedup vs baseline: 2.2748x; 1.0943x over previous
#include <cuda_runtime.h>
#include <cuda_bf16.h>
#include <cstdint>
#include <math.h>

#define Bsz 32
#define Cch 128
#define OCn 128
#define En  8
#define Tn  256
#define HIDn 64
#define UPn 256
#define Rn  32
#define GHn 8
#define PADW  66
#define PROWS (66*66)

// ---- device scratch ----
__device__ float g_ps [Bsz * 64 * Cch];
__device__ float g_ps2[Bsz * 64 * Cch];
__device__ float g_rw[Bsz * En];
__device__ __align__(16) __nv_bfloat16 g_whi[Bsz * 9 * 2 * OCn * 64];
__device__ __align__(16) __nv_bfloat16 g_wlo[Bsz * 9 * 2 * OCn * 64];
__device__ __align__(16) __nv_bfloat16 g_xthi[(size_t)Bsz * PROWS * Cch];
__device__ __align__(16) __nv_bfloat16 g_xtlo[(size_t)Bsz * PROWS * Cch];

// ---- PTX helpers (baseline PTX only) ----
__device__ __forceinline__ uint32_t smem_u32(const void* p) {
    uint32_t a;
    asm("{ .reg .u64 t; cvta.to.shared.u64 t, %1; cvt.u32.u64 %0, t; }" : "=r"(a) : "l"(p));
    return a;
}
__device__ __forceinline__ void cp16(uint32_t dst, const void* src) {
    asm volatile("cp.async.cg.shared.global [%0], [%1], 16;" :: "r"(dst), "l"(src));
}
__device__ __forceinline__ void cp_commit() {
    asm volatile("cp.async.commit_group;" ::: "memory");
}
__device__ __forceinline__ void cp_wait1() {
    asm volatile("cp.async.wait_group 1;" ::: "memory");
}
__device__ __forceinline__ void cp_wait0() {
    asm volatile("cp.async.wait_group 0;" ::: "memory");
}
__device__ __forceinline__ void ldsm4(uint32_t* r, uint32_t addr) {
    asm volatile("ldmatrix.sync.aligned.m8n8.x4.shared.b16 {%0,%1,%2,%3}, [%4];"
                 : "=r"(r[0]), "=r"(r[1]), "=r"(r[2]), "=r"(r[3]) : "r"(addr));
}
__device__ __forceinline__ void mma_bf16(float* d, const uint32_t* a, const uint32_t* b) {
    asm volatile(
        "mma.sync.aligned.m16n8k16.row.col.f32.bf16.bf16.f32 "
        "{%0,%1,%2,%3}, {%4,%5,%6,%7}, {%8,%9}, {%0,%1,%2,%3};"
        : "+f"(d[0]), "+f"(d[1]), "+f"(d[2]), "+f"(d[3])
        : "r"(a[0]), "r"(a[1]), "r"(a[2]), "r"(a[3]), "r"(b[0]), "r"(b[1]));
}
__device__ __forceinline__ uint32_t swz(uint32_t off) { return off ^ ((off >> 3) & 0x70); }

// ============================================================
// Launch 1: prep = transpose + partial stats + border zeroing
// ============================================================
__global__ void prep_kernel(const float* __restrict__ x) {
    __shared__ float s[128][65];
    int y = blockIdx.x, b = blockIdx.y, tid = threadIdx.x;
    const float* xb = x + (size_t)b * Cch * 4096;
    for (int i = tid; i < 8192; i += 256) {
        int c = i >> 6, xx = i & 63;
        s[c][xx] = xb[(size_t)c * 4096 + y * 64 + xx];
    }
    __syncthreads();

    if (tid < 128) {
        float s1 = 0.f, s2 = 0.f;
        #pragma unroll 8
        for (int xx = 0; xx < 64; xx++) {
            float v = s[tid][xx];
            s1 += v; s2 += v * v;
        }
        int d = (b * 64 + y) * 128 + tid;
        g_ps[d] = s1; g_ps2[d] = s2;
    }

    size_t base = ((size_t)b * PROWS + (size_t)(y + 1) * PADW + 1) * 128;
    for (int i = tid; i < 8192; i += 256) {
        int px = i >> 7, c = i & 127;
        float v = s[c][px];
        __nv_bfloat16 hi = __float2bfloat16(v);
        __nv_bfloat16 lo = __float2bfloat16(v - __bfloat162float(hi));
        size_t d = base + (size_t)px * 128 + c;
        g_xthi[d] = hi; g_xtlo[d] = lo;
    }

    __nv_bfloat16 z = __float2bfloat16(0.f);
    if (tid < 128) {
        size_t r = ((size_t)b * PROWS + (size_t)(y + 1) * PADW) * 128;
        g_xthi[r + tid] = z;             g_xtlo[r + tid] = z;
        g_xthi[r + 65 * 128 + tid] = z;  g_xtlo[r + 65 * 128 + tid] = z;
    }
    if (y == 0) {
        size_t r = (size_t)b * PROWS * 128;
        for (int i = tid; i < 66 * 128; i += 256) { g_xthi[r + i] = z; g_xtlo[r + i] = z; }
    }
    if (y == 63) {
        size_t r = ((size_t)b * PROWS + 65 * PADW) * 128;
        for (int i = tid; i < 66 * 128; i += 256) { g_xthi[r + i] = z; g_xtlo[r + i] = z; }
    }
}

// ============================================================
// Launch 2: router (finalizes stats from partials)
// ============================================================
__global__ void router_kernel(
    const float* __restrict__ time_emb,
    const float* __restrict__ W_q,  const float* __restrict__ W_k,  const float* __restrict__ W_v,
    const float* __restrict__ W_g,  const float* __restrict__ b_g,
    const float* __restrict__ W_a1, const float* __restrict__ b_a1, const float* __restrict__ W_a2,
    const float* __restrict__ W_b1, const float* __restrict__ b_b1, const float* __restrict__ W_b2,
    const float* __restrict__ W_d,  const float* __restrict__ W_out)
{
    int b = blockIdx.x, tid = threadIdx.x;
    __shared__ float te[Tn], sts[2*Cch], xh[HIDn], a1v[GHn], b1v[GHn],
                     tv[Rn], hv[UPn], xm[HIDn], lg[En];
    te[tid] = time_emb[b * Tn + tid];
    if (tid < Cch) {
        float s1 = 0.f, s2 = 0.f;
        for (int y = 0; y < 64; y++) {
            int d = (b * 64 + y) * 128 + tid;
            s1 += g_ps[d]; s2 += g_ps2[d];
        }
        float mu  = s1 * (1.f / 4096.f);
        float var = s2 * (1.f / 4096.f) - mu * mu;
        sts[tid]       = mu;
        sts[Cch + tid] = sqrtf(fmaxf(var, 0.f)) + 1e-6f;
    }
    __syncthreads();
    if (tid < HIDn) {
        float q = 0.f, k = 0.f, v = 0.f;
        for (int j = 0; j < Tn; j++) q += W_q[tid*Tn+j] * te[j];
        for (int j = 0; j < 2*Cch; j++) {
            float s = sts[j];
            k += W_k[tid*2*Cch+j] * s;
            v += W_v[tid*2*Cch+j] * s;
        }
        xh[tid] = v / (1.f + expf(-(q*k)));
    }
    __syncthreads();
    if (tid < GHn) {
        float sa = b_a1[tid], sb = b_b1[tid];
        for (int i = 0; i < HIDn; i++) { sa += W_a1[tid*HIDn+i]*xh[i]; sb += W_b1[tid*HIDn+i]*xh[i]; }
        a1v[tid] = sa / (1.f + expf(-sa));
        b1v[tid] = sb / (1.f + expf(-sb));
    }
    __syncthreads();
    if (tid < Rn) {
        float acc = 0.f;
        for (int i = 0; i < HIDn; i++) {
            const float* wr = W_a2 + (size_t)(i*Rn + tid)*GHn;
            float ai = 0.f;
            #pragma unroll
            for (int g = 0; g < GHn; g++) ai += wr[g]*a1v[g];
            acc += xh[i]*ai;
        }
        tv[tid] = acc;
    }
    __syncthreads();
    {
        float gate = b_g[tid];
        for (int i = 0; i < HIDn; i++) gate += W_g[tid*HIDn+i]*xh[i];
        float dyn = 0.f;
        for (int r = 0; r < Rn; r++) {
            const float* wr = W_b2 + (size_t)(r*UPn + tid)*GHn;
            float bm = 0.f;
            #pragma unroll
            for (int g = 0; g < GHn; g++) bm += wr[g]*b1v[g];
            dyn += tv[r]*bm;
        }
        hv[tid] = (gate / (1.f + expf(-gate))) * dyn;
    }
    __syncthreads();
    if (tid < HIDn) {
        float m = xh[tid];
        for (int o = 0; o < UPn; o++) m += W_d[tid*UPn+o]*hv[o];
        xm[tid] = m;
    }
    __syncthreads();
    if (tid < En) {
        float l = 0.f;
        for (int i = 0; i < HIDn; i++) l += W_out[tid*HIDn+i]*xm[i];
        lg[tid] = l;
    }
    __syncthreads();
    if (tid == 0) {
        float mx = lg[0];
        for (int e = 1; e < En; e++) mx = fmaxf(mx, lg[e]);
        float ex[En]; float s = 0.f;
        for (int e = 0; e < En; e++) { ex[e] = expf(lg[e]-mx); s += ex[e]; }
        float inv = 1.f / s;
        for (int e = 0; e < En; e++) g_rw[b*En+e] = ex[e]*inv;
    }
}

// ============================================================
// Launch 3: mix -> bf16 hi/lo tiles  [b][tap][chunk][oc][64c]
// ============================================================
__global__ void mix_kernel(const float* __restrict__ expert_w) {
    int idx = blockIdx.x * 256 + threadIdx.x;
    int b  = idx >> 14;
    int oc = (idx >> 7) & 127;
    int c  = idx & 127;
    float acc[9];
    #pragma unroll
    for (int k = 0; k < 9; k++) acc[k] = 0.f;
    #pragma unroll
    for (int e = 0; e < En; e++) {
        float w = g_rw[b*En + e];
        const float* src = expert_w + (size_t)((e*128 + oc)*128 + c) * 9;
        #pragma unroll
        for (int k = 0; k < 9; k++) acc[k] += w * src[k];
    }
    int cx = c >> 6, cl = c & 63;
    #pragma unroll
    for (int k = 0; k < 9; k++) {
        int d = ((b*9 + k)*2 + cx)*8192 + oc*64 + cl;
        __nv_bfloat16 hi = __float2bfloat16(acc[k]);
        __nv_bfloat16 lo = __float2bfloat16(acc[k] - __bfloat162float(hi));
        g_whi[d] = hi; g_wlo[d] = lo;
    }
}

// ============================================================
// Launch 4: conv via mma.sync bf16 (HMMA)
// CTA = (1 image row, b), 128 threads (2x2 warps), M=128oc x N=64px.
// Stage 48KB (Ah16|Al16|Bh8|Bl8), 2 stages = 96KB -> 2 CTAs/SM.
// ============================================================
#define STG  49152
#define SA_H 0
#define SA_L 16384
#define SB_H 32768
#define SB_L 40960
#define CONV_SMEM (2*STG)

__global__ void __launch_bounds__(128)
conv_mma_kernel(float* __restrict__ out)
{
    extern __shared__ char dsm[];
    const uint32_t sb = smem_u32(dsm);
    const int tid  = threadIdx.x;
    const int lane = tid & 31;
    const int wid  = tid >> 5;
    const int wm   = wid & 1;          // 64-oc block
    const int wn   = wid >> 1;         // 0..1 : 32-px block
    const int b    = blockIdx.y;
    const int y    = blockIdx.x;       // one image row per CTA

    const char* xh_base = (const char*)g_xthi + (size_t)b * PROWS * 256;
    const char* xl_base = (const char*)g_xtlo + (size_t)b * PROWS * 256;

    float acc[4][4][4];
    #pragma unroll
    for (int mi = 0; mi < 4; mi++)
        #pragma unroll
        for (int ni = 0; ni < 4; ni++)
            #pragma unroll
            for (int k = 0; k < 4; k++) acc[mi][ni][k] = 0.f;

    auto load_chunk = [&](int ch, int s) {
        int tap = ch >> 1, cx = ch & 1;
        int dy = tap / 3, dx = tap % 3;
        uint32_t so = sb + s * STG;
        const char* ah = (const char*)g_whi + (size_t)((b*9 + tap)*2 + cx) * 16384;
        const char* al = (const char*)g_wlo + (size_t)((b*9 + tap)*2 + cx) * 16384;
        for (int i = tid; i < 1024; i += 128) {
            uint32_t d = swz((uint32_t)i * 16);
            cp16(so + SA_H + d, ah + i * 16);
            cp16(so + SA_L + d, al + i * 16);
        }
        // B: 64 px rows x 128B
        for (int i = tid; i < 512; i += 128) {
            int lr = i >> 3, u = i & 7;
            int p = (y + dy) * PADW + dx + lr;
            size_t g = (size_t)p * 256 + cx * 128 + u * 16;
            uint32_t d = swz((uint32_t)i * 16);
            cp16(so + SB_H + d, xh_base + g);
            cp16(so + SB_L + d, xl_base + g);
        }
        cp_commit();
    };

    load_chunk(0, 0);

    for (int ch = 0; ch < 18; ch++) {
        if (ch < 17) load_chunk(ch + 1, (ch + 1) & 1);
        if (ch < 17) cp_wait1(); else cp_wait0();
        __syncthreads();

        uint32_t so = sb + (ch & 1) * STG;
        int arow = wm * 64 + (lane & 15);
        int acol16 = (lane >> 4) * 16;
        int brow = wn * 32 + ((lane >> 4) << 3) + (lane & 7);
        int bcol16 = ((lane >> 3) & 1) * 16;

        #pragma unroll
        for (int ks = 0; ks < 4; ks++) {
            uint32_t ah[4][4], al[4][4], bh[4][2], bl[4][2];
            #pragma unroll
            for (int mi = 0; mi < 4; mi++) {
                uint32_t off = swz((uint32_t)(arow + mi * 16) * 128 + ks * 32 + acol16);
                ldsm4(ah[mi], so + SA_H + off);
                ldsm4(al[mi], so + SA_L + off);
            }
            #pragma unroll
            for (int np = 0; np < 2; np++) {
                uint32_t off = swz((uint32_t)(brow + np * 16) * 128 + ks * 32 + bcol16);
                uint32_t t[4];
                ldsm4(t, so + SB_H + off);
                bh[2*np][0] = t[0]; bh[2*np][1] = t[1];
                bh[2*np+1][0] = t[2]; bh[2*np+1][1] = t[3];
                ldsm4(t, so + SB_L + off);
                bl[2*np][0] = t[0]; bl[2*np][1] = t[1];
                bl[2*np+1][0] = t[2]; bl[2*np+1][1] = t[3];
            }
            #pragma unroll
            for (int mi = 0; mi < 4; mi++)
                #pragma unroll
                for (int ni = 0; ni < 4; ni++) {
                    mma_bf16(acc[mi][ni], ah[mi], bh[ni]);
                    mma_bf16(acc[mi][ni], ah[mi], bl[ni]);
                    mma_bf16(acc[mi][ni], al[mi], bh[ni]);
                }
        }
        __syncthreads();
    }

    int gid = lane >> 2, q = lane & 3;
    #pragma unroll
    for (int mi = 0; mi < 4; mi++) {
        int oc = wm * 64 + mi * 16 + gid;
        #pragma unroll
        for (int ni = 0; ni < 4; ni++) {
            int px = wn * 32 + ni * 8 + 2 * q;
            size_t base0 = (((size_t)(b * 128 + oc)) * 64 + y) * 64 + px;
            float2 v0 = make_float2(acc[mi][ni][0], acc[mi][ni][1]);
            float2 v1 = make_float2(acc[mi][ni][2], acc[mi][ni][3]);
            *(float2*)(out + base0)          = v0;
            *(float2*)(out + base0 + 8*4096) = v1;   // oc + 8
        }
    }
}

// ============================================================
extern "C" void kernel_launch(void* const* d_in, const int* in_sizes, int n_in,
                              void* d_out, int out_size)
{
    const float* x        = (const float*)d_in[0];
    const float* time_emb = (const float*)d_in[1];
    const float* expert_w = (const float*)d_in[2];
    const float* W_q  = (const float*)d_in[3];
    const float* W_k  = (const float*)d_in[4];
    const float* W_v  = (const float*)d_in[5];
    const float* W_g  = (const float*)d_in[6];
    const float* b_g  = (const float*)d_in[7];
    const float* W_a1 = (const float*)d_in[8];
    const float* b_a1 = (const float*)d_in[9];
    const float* W_a2 = (const float*)d_in[10];
    const float* W_b1 = (const float*)d_in[11];
    const float* b_b1 = (const float*)d_in[12];
    const float* W_b2 = (const float*)d_in[13];
    const float* W_d  = (const float*)d_in[14];
    const float* W_out= (const float*)d_in[15];
    float* out = (float*)d_out;

    cudaFuncSetAttribute(conv_mma_kernel,
                         cudaFuncAttributeMaxDynamicSharedMemorySize, CONV_SMEM);

    prep_kernel<<<dim3(64, Bsz), 256>>>(x);
    router_kernel<<<Bsz, 256>>>(time_emb, W_q, W_k, W_v, W_g, b_g,
                                W_a1, b_a1, W_a2, W_b1, b_b1, W_b2, W_d, W_out);
    mix_kernel<<<(Bsz * 128 * 128) / 256, 256>>>(expert_w);
    conv_mma_kernel<<<dim3(64, Bsz), 128, CONV_SMEM>>>(out);
}

// round 11
// speedup vs baseline: 2.3147x; 1.0175x over previous
#include <cuda_runtime.h>
#include <cuda_bf16.h>
#include <cstdint>
#include <math.h>

#define Bsz 32
#define Cch 128
#define OCn 128
#define En  8
#define Tn  256
#define HIDn 64
#define UPn 256
#define Rn  32
#define GHn 8
#define PADW  66
#define PROWS (66*66)

// ---- device scratch ----
__device__ float g_ps [Bsz * 64 * Cch];
__device__ float g_ps2[Bsz * 64 * Cch];
__device__ float g_rw[Bsz * En];
__device__ __align__(16) __nv_bfloat16 g_whi[Bsz * 9 * 2 * OCn * 64];
__device__ __align__(16) __nv_bfloat16 g_wlo[Bsz * 9 * 2 * OCn * 64];
__device__ __align__(16) __nv_bfloat16 g_xthi[(size_t)Bsz * PROWS * Cch];
__device__ __align__(16) __nv_bfloat16 g_xtlo[(size_t)Bsz * PROWS * Cch];

// ---- PTX helpers (baseline PTX only) ----
__device__ __forceinline__ uint32_t smem_u32(const void* p) {
    uint32_t a;
    asm("{ .reg .u64 t; cvta.to.shared.u64 t, %1; cvt.u32.u64 %0, t; }" : "=r"(a) : "l"(p));
    return a;
}
__device__ __forceinline__ void cp16(uint32_t dst, const void* src) {
    asm volatile("cp.async.cg.shared.global [%0], [%1], 16;" :: "r"(dst), "l"(src));
}
__device__ __forceinline__ void cp_commit() {
    asm volatile("cp.async.commit_group;" ::: "memory");
}
__device__ __forceinline__ void cp_wait1() {
    asm volatile("cp.async.wait_group 1;" ::: "memory");
}
__device__ __forceinline__ void cp_wait0() {
    asm volatile("cp.async.wait_group 0;" ::: "memory");
}
__device__ __forceinline__ void ldsm4(uint32_t* r, uint32_t addr) {
    asm volatile("ldmatrix.sync.aligned.m8n8.x4.shared.b16 {%0,%1,%2,%3}, [%4];"
                 : "=r"(r[0]), "=r"(r[1]), "=r"(r[2]), "=r"(r[3]) : "r"(addr));
}
__device__ __forceinline__ void mma_bf16(float* d, const uint32_t* a, const uint32_t* b) {
    asm volatile(
        "mma.sync.aligned.m16n8k16.row.col.f32.bf16.bf16.f32 "
        "{%0,%1,%2,%3}, {%4,%5,%6,%7}, {%8,%9}, {%0,%1,%2,%3};"
        : "+f"(d[0]), "+f"(d[1]), "+f"(d[2]), "+f"(d[3])
        : "r"(a[0]), "r"(a[1]), "r"(a[2]), "r"(a[3]), "r"(b[0]), "r"(b[1]));
}
__device__ __forceinline__ uint32_t swz(uint32_t off) { return off ^ ((off >> 3) & 0x70); }

// ============================================================
// Launch 1: prep = transpose + partial stats + border zeroing
// ============================================================
__global__ void prep_kernel(const float* __restrict__ x) {
    __shared__ float s[128][65];
    int y = blockIdx.x, b = blockIdx.y, tid = threadIdx.x;
    const float* xb = x + (size_t)b * Cch * 4096;
    for (int i = tid; i < 8192; i += 256) {
        int c = i >> 6, xx = i & 63;
        s[c][xx] = xb[(size_t)c * 4096 + y * 64 + xx];
    }
    __syncthreads();

    if (tid < 128) {
        float s1 = 0.f, s2 = 0.f;
        #pragma unroll 8
        for (int xx = 0; xx < 64; xx++) {
            float v = s[tid][xx];
            s1 += v; s2 += v * v;
        }
        int d = (b * 64 + y) * 128 + tid;
        g_ps[d] = s1; g_ps2[d] = s2;
    }

    // transposed padded NHWC bf16 hi/lo, packed 2-wide stores
    size_t base = ((size_t)b * PROWS + (size_t)(y + 1) * PADW + 1) * 128;
    for (int i = tid; i < 4096; i += 256) {
        int px = i >> 6, cc = (i & 63) * 2;
        float v0 = s[cc][px], v1 = s[cc + 1][px];
        __nv_bfloat16 h0 = __float2bfloat16(v0);
        __nv_bfloat16 h1 = __float2bfloat16(v1);
        __nv_bfloat16 l0 = __float2bfloat16(v0 - __bfloat162float(h0));
        __nv_bfloat16 l1 = __float2bfloat16(v1 - __bfloat162float(h1));
        size_t d = base + (size_t)px * 128 + cc;
        __nv_bfloat162 hp; hp.x = h0; hp.y = h1;
        __nv_bfloat162 lp; lp.x = l0; lp.y = l1;
        *(__nv_bfloat162*)(g_xthi + d) = hp;
        *(__nv_bfloat162*)(g_xtlo + d) = lp;
    }

    __nv_bfloat16 z = __float2bfloat16(0.f);
    if (tid < 128) {
        size_t r = ((size_t)b * PROWS + (size_t)(y + 1) * PADW) * 128;
        g_xthi[r + tid] = z;             g_xtlo[r + tid] = z;
        g_xthi[r + 65 * 128 + tid] = z;  g_xtlo[r + 65 * 128 + tid] = z;
    }
    if (y == 0) {
        size_t r = (size_t)b * PROWS * 128;
        for (int i = tid; i < 66 * 128; i += 256) { g_xthi[r + i] = z; g_xtlo[r + i] = z; }
    }
    if (y == 63) {
        size_t r = ((size_t)b * PROWS + 65 * PADW) * 128;
        for (int i = tid; i < 66 * 128; i += 256) { g_xthi[r + i] = z; g_xtlo[r + i] = z; }
    }
}

// ============================================================
// Launch 2: router (finalizes stats from partials)
// ============================================================
__global__ void router_kernel(
    const float* __restrict__ time_emb,
    const float* __restrict__ W_q,  const float* __restrict__ W_k,  const float* __restrict__ W_v,
    const float* __restrict__ W_g,  const float* __restrict__ b_g,
    const float* __restrict__ W_a1, const float* __restrict__ b_a1, const float* __restrict__ W_a2,
    const float* __restrict__ W_b1, const float* __restrict__ b_b1, const float* __restrict__ W_b2,
    const float* __restrict__ W_d,  const float* __restrict__ W_out)
{
    int b = blockIdx.x, tid = threadIdx.x;
    __shared__ float te[Tn], sts[2*Cch], xh[HIDn], a1v[GHn], b1v[GHn],
                     tv[Rn], hv[UPn], xm[HIDn], lg[En];
    te[tid] = time_emb[b * Tn + tid];
    if (tid < Cch) {
        float s1 = 0.f, s2 = 0.f;
        for (int y = 0; y < 64; y++) {
            int d = (b * 64 + y) * 128 + tid;
            s1 += g_ps[d]; s2 += g_ps2[d];
        }
        float mu  = s1 * (1.f / 4096.f);
        float var = s2 * (1.f / 4096.f) - mu * mu;
        sts[tid]       = mu;
        sts[Cch + tid] = sqrtf(fmaxf(var, 0.f)) + 1e-6f;
    }
    __syncthreads();
    if (tid < HIDn) {
        float q = 0.f, k = 0.f, v = 0.f;
        for (int j = 0; j < Tn; j++) q += W_q[tid*Tn+j] * te[j];
        for (int j = 0; j < 2*Cch; j++) {
            float s = sts[j];
            k += W_k[tid*2*Cch+j] * s;
            v += W_v[tid*2*Cch+j] * s;
        }
        xh[tid] = v / (1.f + expf(-(q*k)));
    }
    __syncthreads();
    if (tid < GHn) {
        float sa = b_a1[tid], sb = b_b1[tid];
        for (int i = 0; i < HIDn; i++) { sa += W_a1[tid*HIDn+i]*xh[i]; sb += W_b1[tid*HIDn+i]*xh[i]; }
        a1v[tid] = sa / (1.f + expf(-sa));
        b1v[tid] = sb / (1.f + expf(-sb));
    }
    __syncthreads();
    if (tid < Rn) {
        float acc = 0.f;
        for (int i = 0; i < HIDn; i++) {
            const float* wr = W_a2 + (size_t)(i*Rn + tid)*GHn;
            float ai = 0.f;
            #pragma unroll
            for (int g = 0; g < GHn; g++) ai += wr[g]*a1v[g];
            acc += xh[i]*ai;
        }
        tv[tid] = acc;
    }
    __syncthreads();
    {
        float gate = b_g[tid];
        for (int i = 0; i < HIDn; i++) gate += W_g[tid*HIDn+i]*xh[i];
        float dyn = 0.f;
        for (int r = 0; r < Rn; r++) {
            const float* wr = W_b2 + (size_t)(r*UPn + tid)*GHn;
            float bm = 0.f;
            #pragma unroll
            for (int g = 0; g < GHn; g++) bm += wr[g]*b1v[g];
            dyn += tv[r]*bm;
        }
        hv[tid] = (gate / (1.f + expf(-gate))) * dyn;
    }
    __syncthreads();
    if (tid < HIDn) {
        float m = xh[tid];
        for (int o = 0; o < UPn; o++) m += W_d[tid*UPn+o]*hv[o];
        xm[tid] = m;
    }
    __syncthreads();
    if (tid < En) {
        float l = 0.f;
        for (int i = 0; i < HIDn; i++) l += W_out[tid*HIDn+i]*xm[i];
        lg[tid] = l;
    }
    __syncthreads();
    if (tid == 0) {
        float mx = lg[0];
        for (int e = 1; e < En; e++) mx = fmaxf(mx, lg[e]);
        float ex[En]; float s = 0.f;
        for (int e = 0; e < En; e++) { ex[e] = expf(lg[e]-mx); s += ex[e]; }
        float inv = 1.f / s;
        for (int e = 0; e < En; e++) g_rw[b*En+e] = ex[e]*inv;
    }
}

// ============================================================
// Launch 3: mix -> bf16 hi/lo tiles  [b][tap][chunk][oc][64c]
// Thread = (oc, c); expert_w read ONCE; loop b in registers.
// ============================================================
__global__ void mix_kernel(const float* __restrict__ expert_w) {
    __shared__ float srw[Bsz * En];   // 256 floats
    int tid = threadIdx.x;
    srw[tid] = g_rw[tid];             // Bsz*En == 256 == blockDim
    __syncthreads();

    int idx = blockIdx.x * 256 + tid;   // 64 blocks x 256 = 16384 = 128oc*128c
    int oc = idx >> 7, c = idx & 127;

    float w[En][9];
    #pragma unroll
    for (int e = 0; e < En; e++) {
        const float* src = expert_w + ((size_t)(e * 128 + oc) * 128 + c) * 9;
        #pragma unroll
        for (int k = 0; k < 9; k++) w[e][k] = src[k];
    }

    int cx = c >> 6, cl = c & 63;
    for (int b = 0; b < Bsz; b++) {
        float rw[En];
        #pragma unroll
        for (int e = 0; e < En; e++) rw[e] = srw[b * En + e];
        #pragma unroll
        for (int k = 0; k < 9; k++) {
            float acc = 0.f;
            #pragma unroll
            for (int e = 0; e < En; e++) acc += rw[e] * w[e][k];
            int d = ((b * 9 + k) * 2 + cx) * 8192 + oc * 64 + cl;
            __nv_bfloat16 hi = __float2bfloat16(acc);
            __nv_bfloat16 lo = __float2bfloat16(acc - __bfloat162float(hi));
            g_whi[d] = hi; g_wlo[d] = lo;
        }
    }
}

// ============================================================
// Launch 4: conv via mma.sync bf16 (HMMA)
// CTA = (1 image row, b), 128 threads (2x2 warps), M=128oc x N=64px.
// Stage 48KB (Ah16|Al16|Bh8|Bl8), 2 stages = 96KB -> 2 CTAs/SM.
// ============================================================
#define STG  49152
#define SA_H 0
#define SA_L 16384
#define SB_H 32768
#define SB_L 40960
#define CONV_SMEM (2*STG)

__global__ void __launch_bounds__(128)
conv_mma_kernel(float* __restrict__ out)
{
    extern __shared__ char dsm[];
    const uint32_t sb = smem_u32(dsm);
    const int tid  = threadIdx.x;
    const int lane = tid & 31;
    const int wid  = tid >> 5;
    const int wm   = wid & 1;
    const int wn   = wid >> 1;
    const int b    = blockIdx.y;
    const int y    = blockIdx.x;

    const char* xh_base = (const char*)g_xthi + (size_t)b * PROWS * 256;
    const char* xl_base = (const char*)g_xtlo + (size_t)b * PROWS * 256;

    float acc[4][4][4];
    #pragma unroll
    for (int mi = 0; mi < 4; mi++)
        #pragma unroll
        for (int ni = 0; ni < 4; ni++)
            #pragma unroll
            for (int k = 0; k < 4; k++) acc[mi][ni][k] = 0.f;

    auto load_chunk = [&](int ch, int s) {
        int tap = ch >> 1, cx = ch & 1;
        int dy = tap / 3, dx = tap % 3;
        uint32_t so = sb + s * STG;
        const char* ah = (const char*)g_whi + (size_t)((b*9 + tap)*2 + cx) * 16384;
        const char* al = (const char*)g_wlo + (size_t)((b*9 + tap)*2 + cx) * 16384;
        for (int i = tid; i < 1024; i += 128) {
            uint32_t d = swz((uint32_t)i * 16);
            cp16(so + SA_H + d, ah + i * 16);
            cp16(so + SA_L + d, al + i * 16);
        }
        for (int i = tid; i < 512; i += 128) {
            int lr = i >> 3, u = i & 7;
            int p = (y + dy) * PADW + dx + lr;
            size_t g = (size_t)p * 256 + cx * 128 + u * 16;
            uint32_t d = swz((uint32_t)i * 16);
            cp16(so + SB_H + d, xh_base + g);
            cp16(so + SB_L + d, xl_base + g);
        }
        cp_commit();
    };

    load_chunk(0, 0);

    for (int ch = 0; ch < 18; ch++) {
        if (ch < 17) load_chunk(ch + 1, (ch + 1) & 1);
        if (ch < 17) cp_wait1(); else cp_wait0();
        __syncthreads();

        uint32_t so = sb + (ch & 1) * STG;
        int arow = wm * 64 + (lane & 15);
        int acol16 = (lane >> 4) * 16;
        int brow = wn * 32 + ((lane >> 4) << 3) + (lane & 7);
        int bcol16 = ((lane >> 3) & 1) * 16;

        #pragma unroll
        for (int ks = 0; ks < 4; ks++) {
            uint32_t ah[4][4], al[4][4], bh[4][2], bl[4][2];
            #pragma unroll
            for (int mi = 0; mi < 4; mi++) {
                uint32_t off = swz((uint32_t)(arow + mi * 16) * 128 + ks * 32 + acol16);
                ldsm4(ah[mi], so + SA_H + off);
                ldsm4(al[mi], so + SA_L + off);
            }
            #pragma unroll
            for (int np = 0; np < 2; np++) {
                uint32_t off = swz((uint32_t)(brow + np * 16) * 128 + ks * 32 + bcol16);
                uint32_t t[4];
                ldsm4(t, so + SB_H + off);
                bh[2*np][0] = t[0]; bh[2*np][1] = t[1];
                bh[2*np+1][0] = t[2]; bh[2*np+1][1] = t[3];
                ldsm4(t, so + SB_L + off);
                bl[2*np][0] = t[0]; bl[2*np][1] = t[1];
                bl[2*np+1][0] = t[2]; bl[2*np+1][1] = t[3];
            }
            #pragma unroll
            for (int mi = 0; mi < 4; mi++)
                #pragma unroll
                for (int ni = 0; ni < 4; ni++) {
                    mma_bf16(acc[mi][ni], ah[mi], bh[ni]);
                    mma_bf16(acc[mi][ni], ah[mi], bl[ni]);
                    mma_bf16(acc[mi][ni], al[mi], bh[ni]);
                }
        }
        __syncthreads();   // protect this stage from next-next chunk's cp.async writes
    }

    int gid = lane >> 2, q = lane & 3;
    #pragma unroll
    for (int mi = 0; mi < 4; mi++) {
        int oc = wm * 64 + mi * 16 + gid;
        #pragma unroll
        for (int ni = 0; ni < 4; ni++) {
            int px = wn * 32 + ni * 8 + 2 * q;
            size_t base0 = (((size_t)(b * 128 + oc)) * 64 + y) * 64 + px;
            float2 v0 = make_float2(acc[mi][ni][0], acc[mi][ni][1]);
            float2 v1 = make_float2(acc[mi][ni][2], acc[mi][ni][3]);
            *(float2*)(out + base0)          = v0;
            *(float2*)(out + base0 + 8*4096) = v1;   // oc + 8
        }
    }
}

// ============================================================
extern "C" void kernel_launch(void* const* d_in, const int* in_sizes, int n_in,
                              void* d_out, int out_size)
{
    const float* x        = (const float*)d_in[0];
    const float* time_emb = (const float*)d_in[1];
    const float* expert_w = (const float*)d_in[2];
    const float* W_q  = (const float*)d_in[3];
    const float* W_k  = (const float*)d_in[4];
    const float* W_v  = (const float*)d_in[5];
    const float* W_g  = (const float*)d_in[6];
    const float* b_g  = (const float*)d_in[7];
    const float* W_a1 = (const float*)d_in[8];
    const float* b_a1 = (const float*)d_in[9];
    const float* W_a2 = (const float*)d_in[10];
    const float* W_b1 = (const float*)d_in[11];
    const float* b_b1 = (const float*)d_in[12];
    const float* W_b2 = (const float*)d_in[13];
    const float* W_d  = (const float*)d_in[14];
    const float* W_out= (const float*)d_in[15];
    float* out = (float*)d_out;

    cudaFuncSetAttribute(conv_mma_kernel,
                         cudaFuncAttributeMaxDynamicSharedMemorySize, CONV_SMEM);

    prep_kernel<<<dim3(64, Bsz), 256>>>(x);
    router_kernel<<<Bsz, 256>>>(time_emb, W_q, W_k, W_v, W_g, b_g,
                                W_a1, b_a1, W_a2, W_b1, b_b1, W_b2, W_d, W_out);
    mix_kernel<<<64, 256>>>(expert_w);
    conv_mma_kernel<<<dim3(64, Bsz), 128, CONV_SMEM>>>(out);
}

// round 12
// speedup vs baseline: 3.6520x; 1.5778x over previous
#include <cuda_runtime.h>
#include <cuda_bf16.h>
#include <cuda_fp16.h>
#include <cstdint>
#include <math.h>

#define Bsz 32
#define Cch 128
#define OCn 128
#define En  8
#define Tn  256
#define HIDn 64
#define UPn 256
#define Rn  32
#define GHn 8
#define PADW  66
#define PROWS (66*66)
#define WSCALE 256.0f
#define WSCALE_INV 0.00390625f

// ---- device scratch ----
__device__ float g_ps [Bsz * 64 * Cch];
__device__ float g_ps2[Bsz * 64 * Cch];
__device__ float g_rw[Bsz * En];
__device__ __align__(16) __half g_wh[Bsz * 9 * 2 * OCn * 64];       // mixed weights, fp16, x256
__device__ __align__(16) __half g_xt[(size_t)Bsz * PROWS * Cch];    // x^T padded, fp16

// ---- PTX helpers (baseline PTX only) ----
__device__ __forceinline__ uint32_t smem_u32(const void* p) {
    uint32_t a;
    asm("{ .reg .u64 t; cvta.to.shared.u64 t, %1; cvt.u32.u64 %0, t; }" : "=r"(a) : "l"(p));
    return a;
}
__device__ __forceinline__ void cp16(uint32_t dst, const void* src) {
    asm volatile("cp.async.cg.shared.global [%0], [%1], 16;" :: "r"(dst), "l"(src));
}
__device__ __forceinline__ void cp_commit() {
    asm volatile("cp.async.commit_group;" ::: "memory");
}
__device__ __forceinline__ void cp_wait1() {
    asm volatile("cp.async.wait_group 1;" ::: "memory");
}
__device__ __forceinline__ void cp_wait0() {
    asm volatile("cp.async.wait_group 0;" ::: "memory");
}
__device__ __forceinline__ void ldsm4(uint32_t* r, uint32_t addr) {
    asm volatile("ldmatrix.sync.aligned.m8n8.x4.shared.b16 {%0,%1,%2,%3}, [%4];"
                 : "=r"(r[0]), "=r"(r[1]), "=r"(r[2]), "=r"(r[3]) : "r"(addr));
}
__device__ __forceinline__ void mma_fp16(float* d, const uint32_t* a, const uint32_t* b) {
    asm volatile(
        "mma.sync.aligned.m16n8k16.row.col.f32.f16.f16.f32 "
        "{%0,%1,%2,%3}, {%4,%5,%6,%7}, {%8,%9}, {%0,%1,%2,%3};"
        : "+f"(d[0]), "+f"(d[1]), "+f"(d[2]), "+f"(d[3])
        : "r"(a[0]), "r"(a[1]), "r"(a[2]), "r"(a[3]), "r"(b[0]), "r"(b[1]));
}
__device__ __forceinline__ uint32_t swz(uint32_t off) { return off ^ ((off >> 3) & 0x70); }

// ============================================================
// Launch 1: prep = transpose + partial stats + border zeroing
// ============================================================
__global__ void prep_kernel(const float* __restrict__ x) {
    __shared__ float s[128][65];
    int y = blockIdx.x, b = blockIdx.y, tid = threadIdx.x;
    const float* xb = x + (size_t)b * Cch * 4096;
    for (int i = tid; i < 8192; i += 256) {
        int c = i >> 6, xx = i & 63;
        s[c][xx] = xb[(size_t)c * 4096 + y * 64 + xx];
    }
    __syncthreads();

    if (tid < 128) {
        float s1 = 0.f, s2 = 0.f;
        #pragma unroll 8
        for (int xx = 0; xx < 64; xx++) {
            float v = s[tid][xx];
            s1 += v; s2 += v * v;
        }
        int d = (b * 64 + y) * 128 + tid;
        g_ps[d] = s1; g_ps2[d] = s2;
    }

    // transposed padded NHWC fp16, packed 2-wide stores
    size_t base = ((size_t)b * PROWS + (size_t)(y + 1) * PADW + 1) * 128;
    for (int i = tid; i < 4096; i += 256) {
        int px = i >> 6, cc = (i & 63) * 2;
        __half2 hp;
        hp.x = __float2half(s[cc][px]);
        hp.y = __float2half(s[cc + 1][px]);
        *(__half2*)(g_xt + base + (size_t)px * 128 + cc) = hp;
    }

    __half z = __float2half(0.f);
    if (tid < 128) {
        size_t r = ((size_t)b * PROWS + (size_t)(y + 1) * PADW) * 128;
        g_xt[r + tid] = z;
        g_xt[r + 65 * 128 + tid] = z;
    }
    if (y == 0) {
        size_t r = (size_t)b * PROWS * 128;
        for (int i = tid; i < 66 * 128; i += 256) g_xt[r + i] = z;
    }
    if (y == 63) {
        size_t r = ((size_t)b * PROWS + 65 * PADW) * 128;
        for (int i = tid; i < 66 * 128; i += 256) g_xt[r + i] = z;
    }
}

// ============================================================
// Launch 2: router (finalizes stats from partials)
// ============================================================
__global__ void router_kernel(
    const float* __restrict__ time_emb,
    const float* __restrict__ W_q,  const float* __restrict__ W_k,  const float* __restrict__ W_v,
    const float* __restrict__ W_g,  const float* __restrict__ b_g,
    const float* __restrict__ W_a1, const float* __restrict__ b_a1, const float* __restrict__ W_a2,
    const float* __restrict__ W_b1, const float* __restrict__ b_b1, const float* __restrict__ W_b2,
    const float* __restrict__ W_d,  const float* __restrict__ W_out)
{
    int b = blockIdx.x, tid = threadIdx.x;
    __shared__ float te[Tn], sts[2*Cch], xh[HIDn], a1v[GHn], b1v[GHn],
                     tv[Rn], hv[UPn], xm[HIDn], lg[En];
    te[tid] = time_emb[b * Tn + tid];
    if (tid < Cch) {
        float s1 = 0.f, s2 = 0.f;
        for (int y = 0; y < 64; y++) {
            int d = (b * 64 + y) * 128 + tid;
            s1 += g_ps[d]; s2 += g_ps2[d];
        }
        float mu  = s1 * (1.f / 4096.f);
        float var = s2 * (1.f / 4096.f) - mu * mu;
        sts[tid]       = mu;
        sts[Cch + tid] = sqrtf(fmaxf(var, 0.f)) + 1e-6f;
    }
    __syncthreads();
    if (tid < HIDn) {
        float q = 0.f, k = 0.f, v = 0.f;
        for (int j = 0; j < Tn; j++) q += W_q[tid*Tn+j] * te[j];
        for (int j = 0; j < 2*Cch; j++) {
            float s = sts[j];
            k += W_k[tid*2*Cch+j] * s;
            v += W_v[tid*2*Cch+j] * s;
        }
        xh[tid] = v / (1.f + expf(-(q*k)));
    }
    __syncthreads();
    if (tid < GHn) {
        float sa = b_a1[tid], sb = b_b1[tid];
        for (int i = 0; i < HIDn; i++) { sa += W_a1[tid*HIDn+i]*xh[i]; sb += W_b1[tid*HIDn+i]*xh[i]; }
        a1v[tid] = sa / (1.f + expf(-sa));
        b1v[tid] = sb / (1.f + expf(-sb));
    }
    __syncthreads();
    if (tid < Rn) {
        float acc = 0.f;
        for (int i = 0; i < HIDn; i++) {
            const float* wr = W_a2 + (size_t)(i*Rn + tid)*GHn;
            float ai = 0.f;
            #pragma unroll
            for (int g = 0; g < GHn; g++) ai += wr[g]*a1v[g];
            acc += xh[i]*ai;
        }
        tv[tid] = acc;
    }
    __syncthreads();
    {
        float gate = b_g[tid];
        for (int i = 0; i < HIDn; i++) gate += W_g[tid*HIDn+i]*xh[i];
        float dyn = 0.f;
        for (int r = 0; r < Rn; r++) {
            const float* wr = W_b2 + (size_t)(r*UPn + tid)*GHn;
            float bm = 0.f;
            #pragma unroll
            for (int g = 0; g < GHn; g++) bm += wr[g]*b1v[g];
            dyn += tv[r]*bm;
        }
        hv[tid] = (gate / (1.f + expf(-gate))) * dyn;
    }
    __syncthreads();
    if (tid < HIDn) {
        float m = xh[tid];
        for (int o = 0; o < UPn; o++) m += W_d[tid*UPn+o]*hv[o];
        xm[tid] = m;
    }
    __syncthreads();
    if (tid < En) {
        float l = 0.f;
        for (int i = 0; i < HIDn; i++) l += W_out[tid*HIDn+i]*xm[i];
        lg[tid] = l;
    }
    __syncthreads();
    if (tid == 0) {
        float mx = lg[0];
        for (int e = 1; e < En; e++) mx = fmaxf(mx, lg[e]);
        float ex[En]; float s = 0.f;
        for (int e = 0; e < En; e++) { ex[e] = expf(lg[e]-mx); s += ex[e]; }
        float inv = 1.f / s;
        for (int e = 0; e < En; e++) g_rw[b*En+e] = ex[e]*inv;
    }
}

// ============================================================
// Launch 3: mix -> fp16 tiles (x256)  [b][tap][chunk][oc][64c]
// Grid (64, 4): blockIdx.y = batch group of 8.
// ============================================================
__global__ void mix_kernel(const float* __restrict__ expert_w) {
    __shared__ float srw[Bsz * En];
    int tid = threadIdx.x;
    srw[tid] = g_rw[tid];
    __syncthreads();

    int idx = blockIdx.x * 256 + tid;
    int oc = idx >> 7, c = idx & 127;
    int b0 = blockIdx.y * 8;

    float w[En][9];
    #pragma unroll
    for (int e = 0; e < En; e++) {
        const float* src = expert_w + ((size_t)(e * 128 + oc) * 128 + c) * 9;
        #pragma unroll
        for (int k = 0; k < 9; k++) w[e][k] = src[k];
    }

    int cx = c >> 6, cl = c & 63;
    for (int b = b0; b < b0 + 8; b++) {
        float rw[En];
        #pragma unroll
        for (int e = 0; e < En; e++) rw[e] = srw[b * En + e];
        #pragma unroll
        for (int k = 0; k < 9; k++) {
            float acc = 0.f;
            #pragma unroll
            for (int e = 0; e < En; e++) acc += rw[e] * w[e][k];
            int d = ((b * 9 + k) * 2 + cx) * 8192 + oc * 64 + cl;
            g_wh[d] = __float2half(acc * WSCALE);
        }
    }
}

// ============================================================
// Launch 4: conv via mma.sync fp16 (single product)
// CTA = (1 image row, b), 128 threads (2x2 warps), M=128oc x N=64px.
// Stage 24KB (A16|B8), 2 stages = 48KB -> up to 4 CTAs/SM.
// ============================================================
#define STG  24576
#define SA   0
#define SB   16384
#define CONV_SMEM (2*STG)

__global__ void __launch_bounds__(128)
conv_mma_kernel(float* __restrict__ out)
{
    extern __shared__ char dsm[];
    const uint32_t sb = smem_u32(dsm);
    const int tid  = threadIdx.x;
    const int lane = tid & 31;
    const int wid  = tid >> 5;
    const int wm   = wid & 1;
    const int wn   = wid >> 1;
    const int b    = blockIdx.y;
    const int y    = blockIdx.x;

    const char* x_base = (const char*)g_xt + (size_t)b * PROWS * 256;

    float acc[4][4][4];
    #pragma unroll
    for (int mi = 0; mi < 4; mi++)
        #pragma unroll
        for (int ni = 0; ni < 4; ni++)
            #pragma unroll
            for (int k = 0; k < 4; k++) acc[mi][ni][k] = 0.f;

    auto load_chunk = [&](int ch, int s) {
        int tap = ch >> 1, cx = ch & 1;
        int dy = tap / 3, dx = tap % 3;
        uint32_t so = sb + s * STG;
        const char* ah = (const char*)g_wh + (size_t)((b*9 + tap)*2 + cx) * 16384;
        for (int i = tid; i < 1024; i += 128) {
            cp16(so + SA + swz((uint32_t)i * 16), ah + i * 16);
        }
        for (int i = tid; i < 512; i += 128) {
            int lr = i >> 3, u = i & 7;
            int p = (y + dy) * PADW + dx + lr;
            size_t g = (size_t)p * 256 + cx * 128 + u * 16;
            cp16(so + SB + swz((uint32_t)i * 16), x_base + g);
        }
        cp_commit();
    };

    load_chunk(0, 0);

    for (int ch = 0; ch < 18; ch++) {
        if (ch < 17) load_chunk(ch + 1, (ch + 1) & 1);
        if (ch < 17) cp_wait1(); else cp_wait0();
        __syncthreads();

        uint32_t so = sb + (ch & 1) * STG;
        int arow = wm * 64 + (lane & 15);
        int acol16 = (lane >> 4) * 16;
        int brow = wn * 32 + ((lane >> 4) << 3) + (lane & 7);
        int bcol16 = ((lane >> 3) & 1) * 16;

        #pragma unroll
        for (int ks = 0; ks < 4; ks++) {
            uint32_t ah[4][4], bh[4][2];
            #pragma unroll
            for (int mi = 0; mi < 4; mi++) {
                uint32_t off = swz((uint32_t)(arow + mi * 16) * 128 + ks * 32 + acol16);
                ldsm4(ah[mi], so + SA + off);
            }
            #pragma unroll
            for (int np = 0; np < 2; np++) {
                uint32_t off = swz((uint32_t)(brow + np * 16) * 128 + ks * 32 + bcol16);
                uint32_t t[4];
                ldsm4(t, so + SB + off);
                bh[2*np][0] = t[0]; bh[2*np][1] = t[1];
                bh[2*np+1][0] = t[2]; bh[2*np+1][1] = t[3];
            }
            #pragma unroll
            for (int mi = 0; mi < 4; mi++)
                #pragma unroll
                for (int ni = 0; ni < 4; ni++)
                    mma_fp16(acc[mi][ni], ah[mi], bh[ni]);
        }
        __syncthreads();
    }

    int gid = lane >> 2, q = lane & 3;
    #pragma unroll
    for (int mi = 0; mi < 4; mi++) {
        int oc = wm * 64 + mi * 16 + gid;
        #pragma unroll
        for (int ni = 0; ni < 4; ni++) {
            int px = wn * 32 + ni * 8 + 2 * q;
            size_t base0 = (((size_t)(b * 128 + oc)) * 64 + y) * 64 + px;
            float2 v0 = make_float2(acc[mi][ni][0] * WSCALE_INV, acc[mi][ni][1] * WSCALE_INV);
            float2 v1 = make_float2(acc[mi][ni][2] * WSCALE_INV, acc[mi][ni][3] * WSCALE_INV);
            *(float2*)(out + base0)          = v0;
            *(float2*)(out + base0 + 8*4096) = v1;   // oc + 8
        }
    }
}

// ============================================================
extern "C" void kernel_launch(void* const* d_in, const int* in_sizes, int n_in,
                              void* d_out, int out_size)
{
    const float* x        = (const float*)d_in[0];
    const float* time_emb = (const float*)d_in[1];
    const float* expert_w = (const float*)d_in[2];
    const float* W_q  = (const float*)d_in[3];
    const float* W_k  = (const float*)d_in[4];
    const float* W_v  = (const float*)d_in[5];
    const float* W_g  = (const float*)d_in[6];
    const float* b_g  = (const float*)d_in[7];
    const float* W_a1 = (const float*)d_in[8];
    const float* b_a1 = (const float*)d_in[9];
    const float* W_a2 = (const float*)d_in[10];
    const float* W_b1 = (const float*)d_in[11];
    const float* b_b1 = (const float*)d_in[12];
    const float* W_b2 = (const float*)d_in[13];
    const float* W_d  = (const float*)d_in[14];
    const float* W_out= (const float*)d_in[15];
    float* out = (float*)d_out;

    cudaFuncSetAttribute(conv_mma_kernel,
                         cudaFuncAttributeMaxDynamicSharedMemorySize, CONV_SMEM);

    prep_kernel<<<dim3(64, Bsz), 256>>>(x);
    router_kernel<<<Bsz, 256>>>(time_emb, W_q, W_k, W_v, W_g, b_g,
                                W_a1, b_a1, W_a2, W_b1, b_b1, W_b2, W_d, W_out);
    mix_kernel<<<dim3(64, 4), 256>>>(expert_w);
    conv_mma_kernel<<<dim3(64, Bsz), 128, CONV_SMEM>>>(out);
}

// round 13
// speedup vs baseline: 3.8492x; 1.0540x over previous
#include <cuda_runtime.h>
#include <cuda_bf16.h>
#include <cuda_fp16.h>
#include <cstdint>
#include <math.h>

#define Bsz 32
#define Cch 128
#define OCn 128
#define En  8
#define Tn  256
#define HIDn 64
#define UPn 256
#define Rn  32
#define GHn 8
#define PADW  66
#define PROWS (66*66)
#define WSCALE 256.0f
#define WSCALE_INV 0.00390625f

// ---- device scratch ----
__device__ float g_ps [Bsz * 64 * Cch];
__device__ float g_ps2[Bsz * 64 * Cch];
__device__ float g_rw[Bsz * En];
__device__ __align__(16) __half g_wh[Bsz * 9 * 2 * OCn * 64];       // mixed weights, fp16, x256
__device__ __align__(16) __half g_xt[(size_t)Bsz * PROWS * Cch];    // x^T padded, fp16

// ---- PTX helpers (baseline PTX only) ----
__device__ __forceinline__ uint32_t smem_u32(const void* p) {
    uint32_t a;
    asm("{ .reg .u64 t; cvta.to.shared.u64 t, %1; cvt.u32.u64 %0, t; }" : "=r"(a) : "l"(p));
    return a;
}
__device__ __forceinline__ void cp16(uint32_t dst, const void* src) {
    asm volatile("cp.async.cg.shared.global [%0], [%1], 16;" :: "r"(dst), "l"(src));
}
__device__ __forceinline__ void cp_commit() {
    asm volatile("cp.async.commit_group;" ::: "memory");
}
__device__ __forceinline__ void cp_wait1() {
    asm volatile("cp.async.wait_group 1;" ::: "memory");
}
__device__ __forceinline__ void cp_wait0() {
    asm volatile("cp.async.wait_group 0;" ::: "memory");
}
__device__ __forceinline__ void ldsm4(uint32_t* r, uint32_t addr) {
    asm volatile("ldmatrix.sync.aligned.m8n8.x4.shared.b16 {%0,%1,%2,%3}, [%4];"
                 : "=r"(r[0]), "=r"(r[1]), "=r"(r[2]), "=r"(r[3]) : "r"(addr));
}
__device__ __forceinline__ void mma_fp16(float* d, const uint32_t* a, const uint32_t* b) {
    asm volatile(
        "mma.sync.aligned.m16n8k16.row.col.f32.f16.f16.f32 "
        "{%0,%1,%2,%3}, {%4,%5,%6,%7}, {%8,%9}, {%0,%1,%2,%3};"
        : "+f"(d[0]), "+f"(d[1]), "+f"(d[2]), "+f"(d[3])
        : "r"(a[0]), "r"(a[1]), "r"(a[2]), "r"(a[3]), "r"(b[0]), "r"(b[1]));
}
__device__ __forceinline__ uint32_t swz(uint32_t off) { return off ^ ((off >> 3) & 0x70); }

// ============================================================
// Launch 1: prep = transpose + partial stats + border zeroing
// ============================================================
__global__ void prep_kernel(const float* __restrict__ x) {
    __shared__ float s[128][65];
    int y = blockIdx.x, b = blockIdx.y, tid = threadIdx.x;
    const float* xb = x + (size_t)b * Cch * 4096;
    for (int i = tid; i < 8192; i += 256) {
        int c = i >> 6, xx = i & 63;
        s[c][xx] = xb[(size_t)c * 4096 + y * 64 + xx];
    }
    __syncthreads();

    if (tid < 128) {
        float s1 = 0.f, s2 = 0.f;
        #pragma unroll 8
        for (int xx = 0; xx < 64; xx++) {
            float v = s[tid][xx];
            s1 += v; s2 += v * v;
        }
        int d = (b * 64 + y) * 128 + tid;
        g_ps[d] = s1; g_ps2[d] = s2;
    }

    size_t base = ((size_t)b * PROWS + (size_t)(y + 1) * PADW + 1) * 128;
    for (int i = tid; i < 4096; i += 256) {
        int px = i >> 6, cc = (i & 63) * 2;
        __half2 hp;
        hp.x = __float2half(s[cc][px]);
        hp.y = __float2half(s[cc + 1][px]);
        *(__half2*)(g_xt + base + (size_t)px * 128 + cc) = hp;
    }

    __half z = __float2half(0.f);
    if (tid < 128) {
        size_t r = ((size_t)b * PROWS + (size_t)(y + 1) * PADW) * 128;
        g_xt[r + tid] = z;
        g_xt[r + 65 * 128 + tid] = z;
    }
    if (y == 0) {
        size_t r = (size_t)b * PROWS * 128;
        for (int i = tid; i < 66 * 128; i += 256) g_xt[r + i] = z;
    }
    if (y == 63) {
        size_t r = ((size_t)b * PROWS + 65 * PADW) * 128;
        for (int i = tid; i < 66 * 128; i += 256) g_xt[r + i] = z;
    }
}

// ============================================================
// Launch 2: router (finalizes stats from partials)
// ============================================================
__global__ void router_kernel(
    const float* __restrict__ time_emb,
    const float* __restrict__ W_q,  const float* __restrict__ W_k,  const float* __restrict__ W_v,
    const float* __restrict__ W_g,  const float* __restrict__ b_g,
    const float* __restrict__ W_a1, const float* __restrict__ b_a1, const float* __restrict__ W_a2,
    const float* __restrict__ W_b1, const float* __restrict__ b_b1, const float* __restrict__ W_b2,
    const float* __restrict__ W_d,  const float* __restrict__ W_out)
{
    int b = blockIdx.x, tid = threadIdx.x;
    __shared__ float te[Tn], sts[2*Cch], xh[HIDn], a1v[GHn], b1v[GHn],
                     tv[Rn], hv[UPn], xm[HIDn], lg[En];
    te[tid] = time_emb[b * Tn + tid];
    if (tid < Cch) {
        float s1 = 0.f, s2 = 0.f;
        for (int y = 0; y < 64; y++) {
            int d = (b * 64 + y) * 128 + tid;
            s1 += g_ps[d]; s2 += g_ps2[d];
        }
        float mu  = s1 * (1.f / 4096.f);
        float var = s2 * (1.f / 4096.f) - mu * mu;
        sts[tid]       = mu;
        sts[Cch + tid] = sqrtf(fmaxf(var, 0.f)) + 1e-6f;
    }
    __syncthreads();
    if (tid < HIDn) {
        float q = 0.f, k = 0.f, v = 0.f;
        for (int j = 0; j < Tn; j++) q += W_q[tid*Tn+j] * te[j];
        for (int j = 0; j < 2*Cch; j++) {
            float s = sts[j];
            k += W_k[tid*2*Cch+j] * s;
            v += W_v[tid*2*Cch+j] * s;
        }
        xh[tid] = v / (1.f + expf(-(q*k)));
    }
    __syncthreads();
    if (tid < GHn) {
        float sa = b_a1[tid], sb = b_b1[tid];
        for (int i = 0; i < HIDn; i++) { sa += W_a1[tid*HIDn+i]*xh[i]; sb += W_b1[tid*HIDn+i]*xh[i]; }
        a1v[tid] = sa / (1.f + expf(-sa));
        b1v[tid] = sb / (1.f + expf(-sb));
    }
    __syncthreads();
    if (tid < Rn) {
        float acc = 0.f;
        for (int i = 0; i < HIDn; i++) {
            const float* wr = W_a2 + (size_t)(i*Rn + tid)*GHn;
            float ai = 0.f;
            #pragma unroll
            for (int g = 0; g < GHn; g++) ai += wr[g]*a1v[g];
            acc += xh[i]*ai;
        }
        tv[tid] = acc;
    }
    __syncthreads();
    {
        float gate = b_g[tid];
        for (int i = 0; i < HIDn; i++) gate += W_g[tid*HIDn+i]*xh[i];
        float dyn = 0.f;
        for (int r = 0; r < Rn; r++) {
            const float* wr = W_b2 + (size_t)(r*UPn + tid)*GHn;
            float bm = 0.f;
            #pragma unroll
            for (int g = 0; g < GHn; g++) bm += wr[g]*b1v[g];
            dyn += tv[r]*bm;
        }
        hv[tid] = (gate / (1.f + expf(-gate))) * dyn;
    }
    __syncthreads();
    if (tid < HIDn) {
        float m = xh[tid];
        for (int o = 0; o < UPn; o++) m += W_d[tid*UPn+o]*hv[o];
        xm[tid] = m;
    }
    __syncthreads();
    if (tid < En) {
        float l = 0.f;
        for (int i = 0; i < HIDn; i++) l += W_out[tid*HIDn+i]*xm[i];
        lg[tid] = l;
    }
    __syncthreads();
    if (tid == 0) {
        float mx = lg[0];
        for (int e = 1; e < En; e++) mx = fmaxf(mx, lg[e]);
        float ex[En]; float s = 0.f;
        for (int e = 0; e < En; e++) { ex[e] = expf(lg[e]-mx); s += ex[e]; }
        float inv = 1.f / s;
        for (int e = 0; e < En; e++) g_rw[b*En+e] = ex[e]*inv;
    }
}

// ============================================================
// Launch 3: mix -> fp16 tiles (x256)  [b][tap][chunk][oc][64c]
// ============================================================
__global__ void mix_kernel(const float* __restrict__ expert_w) {
    __shared__ float srw[Bsz * En];
    int tid = threadIdx.x;
    srw[tid] = g_rw[tid];
    __syncthreads();

    int idx = blockIdx.x * 256 + tid;
    int oc = idx >> 7, c = idx & 127;
    int b0 = blockIdx.y * 8;

    float w[En][9];
    #pragma unroll
    for (int e = 0; e < En; e++) {
        const float* src = expert_w + ((size_t)(e * 128 + oc) * 128 + c) * 9;
        #pragma unroll
        for (int k = 0; k < 9; k++) w[e][k] = src[k];
    }

    int cx = c >> 6, cl = c & 63;
    for (int b = b0; b < b0 + 8; b++) {
        float rw[En];
        #pragma unroll
        for (int e = 0; e < En; e++) rw[e] = srw[b * En + e];
        #pragma unroll
        for (int k = 0; k < 9; k++) {
            float acc = 0.f;
            #pragma unroll
            for (int e = 0; e < En; e++) acc += rw[e] * w[e][k];
            int d = ((b * 9 + k) * 2 + cx) * 8192 + oc * 64 + cl;
            g_wh[d] = __float2half(acc * WSCALE);
        }
    }
}

// ============================================================
// Launch 4: conv via mma.sync fp16
// CTA = (2 image rows, b), 128 threads (2x2 warps), warp tile 64oc x 64px.
// Stage 32KB (A16|B16), 2 stages = 64KB -> 2 CTAs/SM (regfile-capped).
// ============================================================
#define STG  32768
#define SA   0
#define SB   16384
#define CONV_SMEM (2*STG)

__global__ void __launch_bounds__(128)
conv_mma_kernel(float* __restrict__ out)
{
    extern __shared__ char dsm[];
    const uint32_t sb = smem_u32(dsm);
    const int tid  = threadIdx.x;
    const int lane = tid & 31;
    const int wid  = tid >> 5;
    const int wm   = wid & 1;          // 64-oc block
    const int wn   = wid >> 1;         // 0..1 : 64-px block (= image row select)
    const int b    = blockIdx.y;
    const int y0   = blockIdx.x * 2;   // two image rows per CTA

    const char* x_base = (const char*)g_xt + (size_t)b * PROWS * 256;

    float acc[4][8][4];
    #pragma unroll
    for (int mi = 0; mi < 4; mi++)
        #pragma unroll
        for (int ni = 0; ni < 8; ni++)
            #pragma unroll
            for (int k = 0; k < 4; k++) acc[mi][ni][k] = 0.f;

    auto load_chunk = [&](int ch, int s) {
        int tap = ch >> 1, cx = ch & 1;
        int dy = tap / 3, dx = tap % 3;
        uint32_t so = sb + s * STG;
        const char* ah = (const char*)g_wh + (size_t)((b*9 + tap)*2 + cx) * 16384;
        for (int i = tid; i < 1024; i += 128) {
            cp16(so + SA + swz((uint32_t)i * 16), ah + i * 16);
        }
        // B: 128 px rows (2 image rows) x 128B
        for (int i = tid; i < 1024; i += 128) {
            int lr = i >> 3, u = i & 7;
            int p = (y0 + (lr >> 6) + dy) * PADW + dx + (lr & 63);
            size_t g = (size_t)p * 256 + cx * 128 + u * 16;
            cp16(so + SB + swz((uint32_t)i * 16), x_base + g);
        }
        cp_commit();
    };

    load_chunk(0, 0);

    for (int ch = 0; ch < 18; ch++) {
        if (ch < 17) load_chunk(ch + 1, (ch + 1) & 1);
        if (ch < 17) cp_wait1(); else cp_wait0();
        __syncthreads();

        uint32_t so = sb + (ch & 1) * STG;
        int arow = wm * 64 + (lane & 15);
        int acol16 = (lane >> 4) * 16;
        int brow = wn * 64 + ((lane >> 4) << 3) + (lane & 7);
        int bcol16 = ((lane >> 3) & 1) * 16;

        #pragma unroll
        for (int ks = 0; ks < 4; ks++) {
            uint32_t ah[4][4], bh[8][2];
            #pragma unroll
            for (int mi = 0; mi < 4; mi++) {
                uint32_t off = swz((uint32_t)(arow + mi * 16) * 128 + ks * 32 + acol16);
                ldsm4(ah[mi], so + SA + off);
            }
            #pragma unroll
            for (int np = 0; np < 4; np++) {
                uint32_t off = swz((uint32_t)(brow + np * 16) * 128 + ks * 32 + bcol16);
                uint32_t t[4];
                ldsm4(t, so + SB + off);
                bh[2*np][0] = t[0]; bh[2*np][1] = t[1];
                bh[2*np+1][0] = t[2]; bh[2*np+1][1] = t[3];
            }
            #pragma unroll
            for (int mi = 0; mi < 4; mi++)
                #pragma unroll
                for (int ni = 0; ni < 8; ni++)
                    mma_fp16(acc[mi][ni], ah[mi], bh[ni]);
        }
        __syncthreads();
    }

    // epilogue: y = y0 + wn, x = ni*8 + 2q
    int gid = lane >> 2, q = lane & 3;
    int y = y0 + wn;
    #pragma unroll
    for (int mi = 0; mi < 4; mi++) {
        int oc = wm * 64 + mi * 16 + gid;
        #pragma unroll
        for (int ni = 0; ni < 8; ni++) {
            int xc = ni * 8 + 2 * q;
            size_t base0 = (((size_t)(b * 128 + oc)) * 64 + y) * 64 + xc;
            float2 v0 = make_float2(acc[mi][ni][0] * WSCALE_INV, acc[mi][ni][1] * WSCALE_INV);
            float2 v1 = make_float2(acc[mi][ni][2] * WSCALE_INV, acc[mi][ni][3] * WSCALE_INV);
            *(float2*)(out + base0)          = v0;
            *(float2*)(out + base0 + 8*4096) = v1;   // oc + 8
        }
    }
}

// ============================================================
extern "C" void kernel_launch(void* const* d_in, const int* in_sizes, int n_in,
                              void* d_out, int out_size)
{
    const float* x        = (const float*)d_in[0];
    const float* time_emb = (const float*)d_in[1];
    const float* expert_w = (const float*)d_in[2];
    const float* W_q  = (const float*)d_in[3];
    const float* W_k  = (const float*)d_in[4];
    const float* W_v  = (const float*)d_in[5];
    const float* W_g  = (const float*)d_in[6];
    const float* b_g  = (const float*)d_in[7];
    const float* W_a1 = (const float*)d_in[8];
    const float* b_a1 = (const float*)d_in[9];
    const float* W_a2 = (const float*)d_in[10];
    const float* W_b1 = (const float*)d_in[11];
    const float* b_b1 = (const float*)d_in[12];
    const float* W_b2 = (const float*)d_in[13];
    const float* W_d  = (const float*)d_in[14];
    const float* W_out= (const float*)d_in[15];
    float* out = (float*)d_out;

    cudaFuncSetAttribute(conv_mma_kernel,
                         cudaFuncAttributeMaxDynamicSharedMemorySize, CONV_SMEM);

    prep_kernel<<<dim3(64, Bsz), 256>>>(x);
    router_kernel<<<Bsz, 256>>>(time_emb, W_q, W_k, W_v, W_g, b_g,
                                W_a1, b_a1, W_a2, W_b1, b_b1, W_b2, W_d, W_out);
    mix_kernel<<<dim3(64, 4), 256>>>(expert_w);
    conv_mma_kernel<<<dim3(32, Bsz), 128, CONV_SMEM>>>(out);
}